// round 2
// baseline (speedup 1.0000x reference)
#include <cuda_runtime.h>

#define NN 100000
#define EE_MAX 1600000
#define DD 128
#define NB_SCAN 98   // ceil(100000/1024)

// -------- scratch (device globals; no allocation allowed) --------
__device__ float g_S[(size_t)NN * DD];   // scaled features hs = (X@W)*dinv[row]
__device__ float g_H[(size_t)NN * DD];   // layer output h
__device__ float g_dinv[NN];
__device__ int   g_count[NN];
__device__ int   g_rowptr[NN + 1];
__device__ int   g_cursor[NN];
__device__ int   g_col[EE_MAX];
__device__ int   g_bsum[NB_SCAN];
__device__ int   g_boff[NB_SCAN];

// -------- CSR build --------
__global__ void k_zero_counts() {
    int i = blockIdx.x * blockDim.x + threadIdx.x;
    if (i < NN) g_count[i] = 0;
}

__global__ void k_degree(const int* __restrict__ dst, int E) {
    int e = blockIdx.x * blockDim.x + threadIdx.x;
    if (e < E) atomicAdd(&g_count[dst[e]], 1);
}

// block-local exclusive scan of counts (1024/block), block totals to g_bsum
__global__ void k_scan1(int n) {
    __shared__ int s[1024];
    int i = blockIdx.x * 1024 + threadIdx.x;
    int v = (i < n) ? g_count[i] : 0;
    s[threadIdx.x] = v;
    __syncthreads();
    #pragma unroll
    for (int off = 1; off < 1024; off <<= 1) {
        int t = (threadIdx.x >= off) ? s[threadIdx.x - off] : 0;
        __syncthreads();
        s[threadIdx.x] += t;
        __syncthreads();
    }
    if (i < n) g_rowptr[i] = s[threadIdx.x] - v;  // exclusive within block
    if (threadIdx.x == 1023) g_bsum[blockIdx.x] = s[1023];
}

__global__ void k_scan2(int nb) {  // single block, 128 threads
    __shared__ int s[128];
    int t = threadIdx.x;
    int v = (t < nb) ? g_bsum[t] : 0;
    s[t] = v;
    __syncthreads();
    #pragma unroll
    for (int off = 1; off < 128; off <<= 1) {
        int tv = (t >= off) ? s[t - off] : 0;
        __syncthreads();
        s[t] += tv;
        __syncthreads();
    }
    if (t < nb) g_boff[t] = s[t] - v;  // exclusive
}

__global__ void k_scan3(int n, int E) {
    int i = blockIdx.x * blockDim.x + threadIdx.x;
    if (i < n) {
        int r = g_rowptr[i] + g_boff[i >> 10];
        g_rowptr[i] = r;
        g_cursor[i] = r;
        g_dinv[i]   = rsqrtf((float)g_count[i] + 1.0f);  // +1 self-loop; always >0
    }
    if (i == 0) g_rowptr[n] = E;
}

__global__ void k_bucket(const int* __restrict__ src, const int* __restrict__ dst, int E) {
    int e = blockIdx.x * blockDim.x + threadIdx.x;
    if (e < E) {
        int pos = atomicAdd(&g_cursor[dst[e]], 1);
        g_col[pos] = src[e];
    }
}

// -------- GEMM: g_S[row,:] = (X[row,:] @ W) * dinv[row] --------
// 64 rows/block, 256 threads; thread = 8 rows x 4 cols; W + X tile in smem.
#define GEMM_SMEM ((16384 + 64 * 132) * 4)

__global__ void k_gemm_scale(const float* __restrict__ X, const float* __restrict__ W, int n) {
    extern __shared__ float sm[];
    float* sW = sm;             // 128*128
    float* sX = sm + 16384;     // 64 rows * 132 (padded)
    int t = threadIdx.x;
    int row0 = blockIdx.x * 64;

    // load W (16384 floats) as float4
    {
        const float4* W4 = (const float4*)W;
        float4* sW4 = (float4*)sW;
        #pragma unroll
        for (int j = t; j < 4096; j += 256) sW4[j] = W4[j];
    }
    // load X tile (64 x 128), pad rows to 132 floats (16B aligned)
    #pragma unroll
    for (int j = t; j < 2048; j += 256) {
        int r = j >> 5, k4 = j & 31;
        int gr = row0 + r;
        float4 v = make_float4(0.f, 0.f, 0.f, 0.f);
        if (gr < n) v = *(const float4*)&X[(size_t)gr * DD + k4 * 4];
        *(float4*)&sX[r * 132 + k4 * 4] = v;
    }
    __syncthreads();

    int tx = t & 31, ty = t >> 5;
    float acc[8][4];
    #pragma unroll
    for (int r = 0; r < 8; r++) { acc[r][0] = acc[r][1] = acc[r][2] = acc[r][3] = 0.f; }

    const float* xb = &sX[ty * 8 * 132];
    #pragma unroll 4
    for (int k = 0; k < 128; k++) {
        float4 w = *(const float4*)&sW[k * 128 + tx * 4];
        #pragma unroll
        for (int r = 0; r < 8; r++) {
            float xv = xb[r * 132 + k];   // warp-broadcast (same ty)
            acc[r][0] = fmaf(xv, w.x, acc[r][0]);
            acc[r][1] = fmaf(xv, w.y, acc[r][1]);
            acc[r][2] = fmaf(xv, w.z, acc[r][2]);
            acc[r][3] = fmaf(xv, w.w, acc[r][3]);
        }
    }
    #pragma unroll
    for (int r = 0; r < 8; r++) {
        int gr = row0 + ty * 8 + r;
        if (gr < n) {
            float s = g_dinv[gr];
            float4 o = make_float4(acc[r][0] * s, acc[r][1] * s, acc[r][2] * s, acc[r][3] * s);
            *(float4*)&g_S[(size_t)gr * DD + tx * 4] = o;
        }
    }
}

// -------- gather: g_H[n,:] = act( dinv[n]*(g_S[n,:] + sum_in g_S[src,:]) + b ) --------
__global__ void k_gather(const float* __restrict__ bias, int n, int do_relu) {
    int w = (blockIdx.x * blockDim.x + threadIdx.x) >> 5;
    int lane = threadIdx.x & 31;
    if (w >= n) return;
    int beg = g_rowptr[w];
    int end = g_rowptr[w + 1];
    float4 acc = *(const float4*)&g_S[(size_t)w * DD + lane * 4];  // self-loop
    for (int j = beg; j < end; j++) {
        int s = __ldg(&g_col[j]);
        float4 v = *(const float4*)&g_S[(size_t)s * DD + lane * 4];
        acc.x += v.x; acc.y += v.y; acc.z += v.z; acc.w += v.w;
    }
    float dn = g_dinv[w];
    float4 b = *(const float4*)&bias[lane * 4];
    float4 o = make_float4(fmaf(acc.x, dn, b.x), fmaf(acc.y, dn, b.y),
                           fmaf(acc.z, dn, b.z), fmaf(acc.w, dn, b.w));
    if (do_relu) {
        o.x = fmaxf(o.x, 0.f); o.y = fmaxf(o.y, 0.f);
        o.z = fmaxf(o.z, 0.f); o.w = fmaxf(o.w, 0.f);
    }
    *(float4*)&g_H[(size_t)w * DD + lane * 4] = o;
}

// -------- pair dot products --------
__global__ void k_pairs(const int* __restrict__ pos, const int* __restrict__ neg,
                        float* __restrict__ out, int P) {
    int q = (blockIdx.x * blockDim.x + threadIdx.x) >> 5;
    int lane = threadIdx.x & 31;
    if (q >= 2 * P) return;
    const int* tab = (q < P) ? pos : neg;
    int p = (q < P) ? q : q - P;
    int a = tab[2 * p];
    int b = tab[2 * p + 1];
    float4 va = *(const float4*)&g_H[(size_t)a * DD + lane * 4];
    float4 vb = *(const float4*)&g_H[(size_t)b * DD + lane * 4];
    float d = va.x * vb.x + va.y * vb.y + va.z * vb.z + va.w * vb.w;
    #pragma unroll
    for (int off = 16; off; off >>= 1) d += __shfl_xor_sync(0xffffffffu, d, off);
    if (lane == 0) out[q] = d;
}

extern "C" void kernel_launch(void* const* d_in, const int* in_sizes, int n_in,
                              void* d_out, int out_size) {
    const float* x   = (const float*)d_in[0];
    const float* W1  = (const float*)d_in[1];
    const float* b1  = (const float*)d_in[2];
    const float* W2  = (const float*)d_in[3];
    const float* b2  = (const float*)d_in[4];
    const int* ei    = (const int*)d_in[5];
    const int* edges = (const int*)d_in[6];
    const int* edneg = (const int*)d_in[7];
    float* out = (float*)d_out;

    int E = in_sizes[5] / 2;
    int P = in_sizes[6] / 2;
    const int* src = ei;
    const int* dst = ei + E;

    cudaFuncSetAttribute(k_gemm_scale, cudaFuncAttributeMaxDynamicSharedMemorySize, GEMM_SMEM);

    void* pH = nullptr;
    cudaGetSymbolAddress(&pH, g_H);

    // CSR build + dinv
    k_zero_counts<<<(NN + 255) / 256, 256>>>();
    k_degree<<<(E + 255) / 256, 256>>>(dst, E);
    k_scan1<<<NB_SCAN, 1024>>>(NN);
    k_scan2<<<1, 128>>>(NB_SCAN);
    k_scan3<<<(NN + 255) / 256, 256>>>(NN, E);
    k_bucket<<<(E + 255) / 256, 256>>>(src, dst, E);

    int gemm_blocks = (NN + 63) / 64;
    int gather_blocks = (NN * 32 + 255) / 256;

    // layer 1
    k_gemm_scale<<<gemm_blocks, 256, GEMM_SMEM>>>(x, W1, NN);
    k_gather<<<gather_blocks, 256>>>(b1, NN, 1);
    // layer 2
    k_gemm_scale<<<gemm_blocks, 256, GEMM_SMEM>>>((const float*)pH, W2, NN);
    k_gather<<<gather_blocks, 256>>>(b2, NN, 0);
    // link prediction
    int pair_blocks = (2 * P * 32 + 255) / 256;
    k_pairs<<<pair_blocks, 256>>>(edges, edneg, out, P);
}

// round 3
// speedup vs baseline: 1.1035x; 1.1035x over previous
#include <cuda_runtime.h>

#define NN 100000
#define EE_MAX 1600000
#define DD 128
#define NB_SCAN 98   // ceil(100000/1024)

// -------- scratch (device globals; no allocation allowed) --------
__device__ float  g_S[(size_t)NN * DD];   // X@W (unscaled)
__device__ float  g_H[(size_t)NN * DD];   // layer output h
__device__ float  g_dinv[NN];
__device__ int    g_count[NN];
__device__ int    g_rowptr[NN + 1];
__device__ int    g_cursor[NN];
__device__ int    g_col[EE_MAX];
__device__ int    g_bsum[NB_SCAN];
__device__ int    g_boff[NB_SCAN];
__device__ float4 g_Wf1[16 * 16 * 32];    // W1 in mma-fragment order (b0hi,b1hi,b0lo,b1lo)
__device__ float4 g_Wf2[16 * 16 * 32];

// -------- tf32 helpers --------
__device__ __forceinline__ unsigned f2tf(float x) {
    unsigned u;
    asm("cvt.rna.tf32.f32 %0, %1;" : "=r"(u) : "f"(x));
    return u;
}
__device__ __forceinline__ void split_tf32(float x, unsigned& hi, unsigned& lo) {
    hi = f2tf(x);
    float r = x - __uint_as_float(hi);
    lo = f2tf(r);
}
__device__ __forceinline__ void mma8(float* c, const unsigned* a, const unsigned* b) {
    asm volatile(
        "mma.sync.aligned.m16n8k8.row.col.f32.tf32.tf32.f32 "
        "{%0,%1,%2,%3}, {%4,%5,%6,%7}, {%8,%9}, {%0,%1,%2,%3};\n"
        : "+f"(c[0]), "+f"(c[1]), "+f"(c[2]), "+f"(c[3])
        : "r"(a[0]), "r"(a[1]), "r"(a[2]), "r"(a[3]), "r"(b[0]), "r"(b[1]));
}

// -------- CSR build --------
__global__ void k_zero_counts() {
    int i = blockIdx.x * blockDim.x + threadIdx.x;
    if (i < NN) g_count[i] = 0;
}

__global__ void k_degree(const int* __restrict__ dst, int E) {
    int e = blockIdx.x * blockDim.x + threadIdx.x;
    if (e < E) atomicAdd(&g_count[dst[e]], 1);
}

__global__ void k_scan1(int n) {
    __shared__ int s[1024];
    int i = blockIdx.x * 1024 + threadIdx.x;
    int v = (i < n) ? g_count[i] : 0;
    s[threadIdx.x] = v;
    __syncthreads();
    #pragma unroll
    for (int off = 1; off < 1024; off <<= 1) {
        int t = (threadIdx.x >= off) ? s[threadIdx.x - off] : 0;
        __syncthreads();
        s[threadIdx.x] += t;
        __syncthreads();
    }
    if (i < n) g_rowptr[i] = s[threadIdx.x] - v;  // exclusive within block
    if (threadIdx.x == 1023) g_bsum[blockIdx.x] = s[1023];
}

__global__ void k_scan2(int nb) {  // single block, 128 threads
    __shared__ int s[128];
    int t = threadIdx.x;
    int v = (t < nb) ? g_bsum[t] : 0;
    s[t] = v;
    __syncthreads();
    #pragma unroll
    for (int off = 1; off < 128; off <<= 1) {
        int tv = (t >= off) ? s[t - off] : 0;
        __syncthreads();
        s[t] += tv;
        __syncthreads();
    }
    if (t < nb) g_boff[t] = s[t] - v;  // exclusive
}

__global__ void k_scan3(int n, int E) {
    int i = blockIdx.x * blockDim.x + threadIdx.x;
    if (i < n) {
        int r = g_rowptr[i] + g_boff[i >> 10];
        g_rowptr[i] = r;
        g_cursor[i] = r;
        g_dinv[i]   = rsqrtf((float)g_count[i] + 1.0f);  // +1 self-loop
    }
    if (i == 0) g_rowptr[n] = E;
}

__global__ void k_bucket(const int* __restrict__ src, const int* __restrict__ dst, int E) {
    int e = blockIdx.x * blockDim.x + threadIdx.x;
    if (e < E) {
        int pos = atomicAdd(&g_cursor[dst[e]], 1);
        g_col[pos] = src[e];
    }
}

// -------- W -> fragment-order hi/lo split --------
// Fragment layout for mma.m16n8k8 B (col-major k8n8): tig = lane&3, g = lane>>2
//   b0 = W[k0+tig][n0+g], b1 = W[k0+tig+4][n0+g]
__global__ void k_wsplit(const float* __restrict__ W, float4* __restrict__ out) {
    int i = blockIdx.x * blockDim.x + threadIdx.x;
    if (i >= 16 * 16 * 32) return;
    int lane = i & 31;
    int tile = i >> 5;
    int ntile = tile & 15;
    int kt = tile >> 4;
    int tig = lane & 3, g = lane >> 2;
    float b0 = W[(kt * 8 + tig) * DD + ntile * 8 + g];
    float b1 = W[(kt * 8 + tig + 4) * DD + ntile * 8 + g];
    unsigned b0h, b0l, b1h, b1l;
    split_tf32(b0, b0h, b0l);
    split_tf32(b1, b1h, b1l);
    out[i] = make_float4(__uint_as_float(b0h), __uint_as_float(b1h),
                         __uint_as_float(b0l), __uint_as_float(b1l));
}

// -------- GEMM (3xTF32 tensor core): out[n,128] = X[n,128] @ W --------
// 128 rows/block, 1024 threads = 32 warps (8 warp-rows x 4 warp-cols),
// warp tile 16 rows x 32 cols (4 n-tiles of 8).
#define GSMEM (128 * 132 * 4 + 16 * 16 * 32 * 16)   // 67584 + 131072 = 198656

__global__ void __launch_bounds__(1024, 1)
k_gemm(const float* __restrict__ X, const float4* __restrict__ Wfrag,
       float* __restrict__ out, int n) {
    extern __shared__ float sm[];
    float*  sX = sm;                          // 128 x 132 (padded)
    float4* sW = (float4*)(sm + 128 * 132);   // 16*16*32 fragment float4s
    int t = threadIdx.x;
    int row0 = blockIdx.x * 128;

    #pragma unroll
    for (int j = t; j < 8192; j += 1024) sW[j] = Wfrag[j];
    #pragma unroll
    for (int j = t; j < 4096; j += 1024) {
        int r = j >> 5, c4 = j & 31;
        int gr = row0 + r;
        float4 v = make_float4(0.f, 0.f, 0.f, 0.f);
        if (gr < n) v = *(const float4*)&X[(size_t)gr * DD + c4 * 4];
        *(float4*)&sX[r * 132 + c4 * 4] = v;
    }
    __syncthreads();

    int lane = t & 31, wid = t >> 5;
    int wr = wid >> 2, wc = wid & 3;
    int g = lane >> 2, tig = lane & 3;

    float c[4][4];
    #pragma unroll
    for (int i = 0; i < 4; i++)
        #pragma unroll
        for (int j = 0; j < 4; j++) c[i][j] = 0.f;

    const float* xb = &sX[(wr * 16 + g) * 132];

    #pragma unroll
    for (int kt = 0; kt < 16; kt++) {
        int k0 = kt * 8;
        // A fragment (m16k8 row-major): a0 (g, tig), a1 (g+8, tig), a2 (g, tig+4), a3 (g+8, tig+4)
        float a0f = xb[k0 + tig];
        float a1f = xb[8 * 132 + k0 + tig];
        float a2f = xb[k0 + tig + 4];
        float a3f = xb[8 * 132 + k0 + tig + 4];
        unsigned ah[4], al[4];
        split_tf32(a0f, ah[0], al[0]);
        split_tf32(a1f, ah[1], al[1]);
        split_tf32(a2f, ah[2], al[2]);
        split_tf32(a3f, ah[3], al[3]);
        #pragma unroll
        for (int nt = 0; nt < 4; nt++) {
            float4 bf = sW[(kt * 16 + wc * 4 + nt) * 32 + lane];
            unsigned bh[2] = {__float_as_uint(bf.x), __float_as_uint(bf.y)};
            unsigned bl[2] = {__float_as_uint(bf.z), __float_as_uint(bf.w)};
            mma8(c[nt], ah, bh);   // hi*hi
            mma8(c[nt], al, bh);   // lo*hi
            mma8(c[nt], ah, bl);   // hi*lo
        }
    }

    int ra = row0 + wr * 16 + g;
    int rb = ra + 8;
    #pragma unroll
    for (int nt = 0; nt < 4; nt++) {
        int col = wc * 32 + nt * 8 + tig * 2;
        if (ra < n) *(float2*)&out[(size_t)ra * DD + col] = make_float2(c[nt][0], c[nt][1]);
        if (rb < n) *(float2*)&out[(size_t)rb * DD + col] = make_float2(c[nt][2], c[nt][3]);
    }
}

// -------- gather: H[w,:] = act( dinv[w]*( dinv[w]*S[w,:] + sum_in dinv[s]*S[s,:] ) + b ) ----
__global__ void k_gather(const float* __restrict__ bias, int n, int do_relu) {
    int w = (blockIdx.x * blockDim.x + threadIdx.x) >> 5;
    int lane = threadIdx.x & 31;
    if (w >= n) return;
    int beg = g_rowptr[w];
    int end = g_rowptr[w + 1];
    float dn = g_dinv[w];
    float4 self = *(const float4*)&g_S[(size_t)w * DD + lane * 4];
    float4 acc = make_float4(dn * self.x, dn * self.y, dn * self.z, dn * self.w);
    for (int j = beg; j < end; j++) {
        int s = __ldg(&g_col[j]);
        float ds = __ldg(&g_dinv[s]);
        float4 v = *(const float4*)&g_S[(size_t)s * DD + lane * 4];
        acc.x = fmaf(ds, v.x, acc.x);
        acc.y = fmaf(ds, v.y, acc.y);
        acc.z = fmaf(ds, v.z, acc.z);
        acc.w = fmaf(ds, v.w, acc.w);
    }
    float4 b = *(const float4*)&bias[lane * 4];
    float4 o = make_float4(fmaf(acc.x, dn, b.x), fmaf(acc.y, dn, b.y),
                           fmaf(acc.z, dn, b.z), fmaf(acc.w, dn, b.w));
    if (do_relu) {
        o.x = fmaxf(o.x, 0.f); o.y = fmaxf(o.y, 0.f);
        o.z = fmaxf(o.z, 0.f); o.w = fmaxf(o.w, 0.f);
    }
    *(float4*)&g_H[(size_t)w * DD + lane * 4] = o;
}

// -------- pair dot products --------
__global__ void k_pairs(const int* __restrict__ pos, const int* __restrict__ neg,
                        float* __restrict__ out, int P) {
    int q = (blockIdx.x * blockDim.x + threadIdx.x) >> 5;
    int lane = threadIdx.x & 31;
    if (q >= 2 * P) return;
    const int* tab = (q < P) ? pos : neg;
    int p = (q < P) ? q : q - P;
    int a = tab[2 * p];
    int b = tab[2 * p + 1];
    float4 va = *(const float4*)&g_H[(size_t)a * DD + lane * 4];
    float4 vb = *(const float4*)&g_H[(size_t)b * DD + lane * 4];
    float d = va.x * vb.x + va.y * vb.y + va.z * vb.z + va.w * vb.w;
    #pragma unroll
    for (int off = 16; off; off >>= 1) d += __shfl_xor_sync(0xffffffffu, d, off);
    if (lane == 0) out[q] = d;
}

extern "C" void kernel_launch(void* const* d_in, const int* in_sizes, int n_in,
                              void* d_out, int out_size) {
    const float* x   = (const float*)d_in[0];
    const float* W1  = (const float*)d_in[1];
    const float* b1  = (const float*)d_in[2];
    const float* W2  = (const float*)d_in[3];
    const float* b2  = (const float*)d_in[4];
    const int* ei    = (const int*)d_in[5];
    const int* edges = (const int*)d_in[6];
    const int* edneg = (const int*)d_in[7];
    float* out = (float*)d_out;

    int E = in_sizes[5] / 2;
    int P = in_sizes[6] / 2;
    const int* src = ei;
    const int* dst = ei + E;

    cudaFuncSetAttribute(k_gemm, cudaFuncAttributeMaxDynamicSharedMemorySize, GSMEM);

    void *pH = nullptr, *pWf1 = nullptr, *pWf2 = nullptr;
    cudaGetSymbolAddress(&pH, g_H);
    cudaGetSymbolAddress(&pWf1, g_Wf1);
    cudaGetSymbolAddress(&pWf2, g_Wf2);

    // W fragment pre-split (tiny) + CSR build + dinv
    k_wsplit<<<(16 * 16 * 32 + 255) / 256, 256>>>(W1, (float4*)pWf1);
    k_wsplit<<<(16 * 16 * 32 + 255) / 256, 256>>>(W2, (float4*)pWf2);
    k_zero_counts<<<(NN + 255) / 256, 256>>>();
    k_degree<<<(E + 255) / 256, 256>>>(dst, E);
    k_scan1<<<NB_SCAN, 1024>>>(NN);
    k_scan2<<<1, 128>>>(NB_SCAN);
    k_scan3<<<(NN + 255) / 256, 256>>>(NN, E);
    k_bucket<<<(E + 255) / 256, 256>>>(src, dst, E);

    int gemm_blocks = (NN + 127) / 128;
    int gather_blocks = (NN * 32 + 255) / 256;

    void* pS = nullptr;
    cudaGetSymbolAddress(&pS, g_S);

    // layer 1
    k_gemm<<<gemm_blocks, 1024, GSMEM>>>(x, (const float4*)pWf1, (float*)pS, NN);
    k_gather<<<gather_blocks, 256>>>(b1, NN, 1);
    // layer 2
    k_gemm<<<gemm_blocks, 1024, GSMEM>>>((const float*)pH, (const float4*)pWf2, (float*)pS, NN);
    k_gather<<<gather_blocks, 256>>>(b2, NN, 0);
    // link prediction
    int pair_blocks = (2 * P * 32 + 255) / 256;
    k_pairs<<<pair_blocks, 256>>>(edges, edneg, out, P);
}

// round 4
// speedup vs baseline: 1.1675x; 1.0580x over previous
#include <cuda_runtime.h>
#include <cuda_fp16.h>

#define NN 100000
#define EE_MAX 1600000
#define DD 128
#define NB_SCAN 98   // ceil(100000/1024)

// -------- scratch (device globals; no allocation allowed) --------
__device__ __half  g_Sh[(size_t)NN * DD];  // X@W, fp16 (scattered-read array)
__device__ float   g_H[(size_t)NN * DD];   // layer-1 output, fp32 (linear-read by GEMM2)
__device__ __half  g_Hh[(size_t)NN * DD];  // layer-2 output, fp16 (scattered-read by pairs)
__device__ float   g_dinv[NN];
__device__ int     g_count[NN];
__device__ int     g_rowptr[NN + 1];
__device__ int     g_cursor[NN];
__device__ int     g_col[EE_MAX];
__device__ int     g_bsum[NB_SCAN];
__device__ int     g_boff[NB_SCAN];
__device__ float4  g_Wf1[16 * 16 * 32];    // W in mma-fragment order (b0hi,b1hi,b0lo,b1lo)
__device__ float4  g_Wf2[16 * 16 * 32];

// -------- tf32 helpers --------
__device__ __forceinline__ unsigned f2tf(float x) {
    unsigned u;
    asm("cvt.rna.tf32.f32 %0, %1;" : "=r"(u) : "f"(x));
    return u;
}
__device__ __forceinline__ void split_tf32(float x, unsigned& hi, unsigned& lo) {
    hi = f2tf(x);
    float r = x - __uint_as_float(hi);
    lo = f2tf(r);
}
__device__ __forceinline__ void mma8(float* c, const unsigned* a, const unsigned* b) {
    asm volatile(
        "mma.sync.aligned.m16n8k8.row.col.f32.tf32.tf32.f32 "
        "{%0,%1,%2,%3}, {%4,%5,%6,%7}, {%8,%9}, {%0,%1,%2,%3};\n"
        : "+f"(c[0]), "+f"(c[1]), "+f"(c[2]), "+f"(c[3])
        : "r"(a[0]), "r"(a[1]), "r"(a[2]), "r"(a[3]), "r"(b[0]), "r"(b[1]));
}

// -------- CSR build --------
__global__ void k_zero_counts() {
    int i = blockIdx.x * blockDim.x + threadIdx.x;
    if (i < NN) g_count[i] = 0;
}

__global__ void k_degree(const int* __restrict__ dst, int E) {
    int e = blockIdx.x * blockDim.x + threadIdx.x;
    if (e < E) atomicAdd(&g_count[dst[e]], 1);
}

__global__ void k_scan1(int n) {
    __shared__ int s[1024];
    int i = blockIdx.x * 1024 + threadIdx.x;
    int v = (i < n) ? g_count[i] : 0;
    s[threadIdx.x] = v;
    __syncthreads();
    #pragma unroll
    for (int off = 1; off < 1024; off <<= 1) {
        int t = (threadIdx.x >= off) ? s[threadIdx.x - off] : 0;
        __syncthreads();
        s[threadIdx.x] += t;
        __syncthreads();
    }
    if (i < n) g_rowptr[i] = s[threadIdx.x] - v;  // exclusive within block
    if (threadIdx.x == 1023) g_bsum[blockIdx.x] = s[1023];
}

__global__ void k_scan2(int nb) {  // single block, 128 threads
    __shared__ int s[128];
    int t = threadIdx.x;
    int v = (t < nb) ? g_bsum[t] : 0;
    s[t] = v;
    __syncthreads();
    #pragma unroll
    for (int off = 1; off < 128; off <<= 1) {
        int tv = (t >= off) ? s[t - off] : 0;
        __syncthreads();
        s[t] += tv;
        __syncthreads();
    }
    if (t < nb) g_boff[t] = s[t] - v;  // exclusive
}

__global__ void k_scan3(int n, int E) {
    int i = blockIdx.x * blockDim.x + threadIdx.x;
    if (i < n) {
        int r = g_rowptr[i] + g_boff[i >> 10];
        g_rowptr[i] = r;
        g_cursor[i] = r;
        g_dinv[i]   = rsqrtf((float)g_count[i] + 1.0f);  // +1 self-loop
    }
    if (i == 0) g_rowptr[n] = E;
}

__global__ void k_bucket(const int* __restrict__ src, const int* __restrict__ dst, int E) {
    int e = blockIdx.x * blockDim.x + threadIdx.x;
    if (e < E) {
        int pos = atomicAdd(&g_cursor[dst[e]], 1);
        g_col[pos] = src[e];
    }
}

// -------- W -> fragment-order hi/lo split --------
__global__ void k_wsplit(const float* __restrict__ W, float4* __restrict__ out) {
    int i = blockIdx.x * blockDim.x + threadIdx.x;
    if (i >= 16 * 16 * 32) return;
    int lane = i & 31;
    int tile = i >> 5;
    int ntile = tile & 15;
    int kt = tile >> 4;
    int tig = lane & 3, g = lane >> 2;
    float b0 = W[(kt * 8 + tig) * DD + ntile * 8 + g];
    float b1 = W[(kt * 8 + tig + 4) * DD + ntile * 8 + g];
    unsigned b0h, b0l, b1h, b1l;
    split_tf32(b0, b0h, b0l);
    split_tf32(b1, b1h, b1l);
    out[i] = make_float4(__uint_as_float(b0h), __uint_as_float(b1h),
                         __uint_as_float(b0l), __uint_as_float(b1l));
}

// -------- GEMM (3xTF32 tensor core): Sh[n,128] = fp16( X[n,128] @ W ) --------
#define GSMEM (128 * 132 * 4 + 16 * 16 * 32 * 16)   // 198656

__global__ void __launch_bounds__(1024, 1)
k_gemm(const float* __restrict__ X, const float4* __restrict__ Wfrag,
       __half* __restrict__ out, int n) {
    extern __shared__ float sm[];
    float*  sX = sm;                          // 128 x 132 (padded)
    float4* sW = (float4*)(sm + 128 * 132);   // fragment float4s
    int t = threadIdx.x;
    int row0 = blockIdx.x * 128;

    #pragma unroll
    for (int j = t; j < 8192; j += 1024) sW[j] = Wfrag[j];
    #pragma unroll
    for (int j = t; j < 4096; j += 1024) {
        int r = j >> 5, c4 = j & 31;
        int gr = row0 + r;
        float4 v = make_float4(0.f, 0.f, 0.f, 0.f);
        if (gr < n) v = *(const float4*)&X[(size_t)gr * DD + c4 * 4];
        *(float4*)&sX[r * 132 + c4 * 4] = v;
    }
    __syncthreads();

    int lane = t & 31, wid = t >> 5;
    int wr = wid >> 2, wc = wid & 3;
    int g = lane >> 2, tig = lane & 3;

    float c[4][4];
    #pragma unroll
    for (int i = 0; i < 4; i++)
        #pragma unroll
        for (int j = 0; j < 4; j++) c[i][j] = 0.f;

    const float* xb = &sX[(wr * 16 + g) * 132];

    #pragma unroll
    for (int kt = 0; kt < 16; kt++) {
        int k0 = kt * 8;
        float a0f = xb[k0 + tig];
        float a1f = xb[8 * 132 + k0 + tig];
        float a2f = xb[k0 + tig + 4];
        float a3f = xb[8 * 132 + k0 + tig + 4];
        unsigned ah[4], al[4];
        split_tf32(a0f, ah[0], al[0]);
        split_tf32(a1f, ah[1], al[1]);
        split_tf32(a2f, ah[2], al[2]);
        split_tf32(a3f, ah[3], al[3]);
        #pragma unroll
        for (int nt = 0; nt < 4; nt++) {
            float4 bf = sW[(kt * 16 + wc * 4 + nt) * 32 + lane];
            unsigned bh[2] = {__float_as_uint(bf.x), __float_as_uint(bf.y)};
            unsigned bl[2] = {__float_as_uint(bf.z), __float_as_uint(bf.w)};
            mma8(c[nt], ah, bh);   // hi*hi
            mma8(c[nt], al, bh);   // lo*hi
            mma8(c[nt], ah, bl);   // hi*lo
        }
    }

    int ra = row0 + wr * 16 + g;
    int rb = ra + 8;
    #pragma unroll
    for (int nt = 0; nt < 4; nt++) {
        int col = wc * 32 + nt * 8 + tig * 2;
        if (ra < n) *(__half2*)&out[(size_t)ra * DD + col] = __floats2half2_rn(c[nt][0], c[nt][1]);
        if (rb < n) *(__half2*)&out[(size_t)rb * DD + col] = __floats2half2_rn(c[nt][2], c[nt][3]);
    }
}

// -------- gather from fp16 S; fp32 accumulate --------
// H[w,:] = act( dinv[w]*( dinv[w]*S[w,:] + sum_in dinv[s]*S[s,:] ) + b )
__device__ __forceinline__ void acc_h4(float4& acc, uint2 u, float ds) {
    float2 f0 = __half22float2(*reinterpret_cast<__half2*>(&u.x));
    float2 f1 = __half22float2(*reinterpret_cast<__half2*>(&u.y));
    acc.x = fmaf(ds, f0.x, acc.x);
    acc.y = fmaf(ds, f0.y, acc.y);
    acc.z = fmaf(ds, f1.x, acc.z);
    acc.w = fmaf(ds, f1.y, acc.w);
}

template <bool RELU_F32OUT>
__global__ void k_gather(const float* __restrict__ bias, int n) {
    int w = (blockIdx.x * blockDim.x + threadIdx.x) >> 5;
    int lane = threadIdx.x & 31;
    if (w >= n) return;
    int beg = g_rowptr[w];
    int end = g_rowptr[w + 1];
    float dn = g_dinv[w];
    // lane covers features [lane*4, lane*4+4) -> 8B (uint2) per fp16 row
    uint2 su = *((const uint2*)&g_Sh[(size_t)w * DD] + lane);
    float4 acc = make_float4(0.f, 0.f, 0.f, 0.f);
    acc_h4(acc, su, dn);  // self-loop
    int j = beg;
    for (; j + 4 <= end; j += 4) {
        int s0 = __ldg(&g_col[j]);
        int s1 = __ldg(&g_col[j + 1]);
        int s2 = __ldg(&g_col[j + 2]);
        int s3 = __ldg(&g_col[j + 3]);
        float d0 = __ldg(&g_dinv[s0]);
        float d1 = __ldg(&g_dinv[s1]);
        float d2 = __ldg(&g_dinv[s2]);
        float d3 = __ldg(&g_dinv[s3]);
        uint2 u0 = *((const uint2*)&g_Sh[(size_t)s0 * DD] + lane);
        uint2 u1 = *((const uint2*)&g_Sh[(size_t)s1 * DD] + lane);
        uint2 u2 = *((const uint2*)&g_Sh[(size_t)s2 * DD] + lane);
        uint2 u3 = *((const uint2*)&g_Sh[(size_t)s3 * DD] + lane);
        acc_h4(acc, u0, d0);
        acc_h4(acc, u1, d1);
        acc_h4(acc, u2, d2);
        acc_h4(acc, u3, d3);
    }
    for (; j < end; j++) {
        int s = __ldg(&g_col[j]);
        float ds = __ldg(&g_dinv[s]);
        uint2 u = *((const uint2*)&g_Sh[(size_t)s * DD] + lane);
        acc_h4(acc, u, ds);
    }
    float4 b = *(const float4*)&bias[lane * 4];
    float4 o = make_float4(fmaf(acc.x, dn, b.x), fmaf(acc.y, dn, b.y),
                           fmaf(acc.z, dn, b.z), fmaf(acc.w, dn, b.w));
    if (RELU_F32OUT) {
        o.x = fmaxf(o.x, 0.f); o.y = fmaxf(o.y, 0.f);
        o.z = fmaxf(o.z, 0.f); o.w = fmaxf(o.w, 0.f);
        *(float4*)&g_H[(size_t)w * DD + lane * 4] = o;
    } else {
        uint2 pk;
        *reinterpret_cast<__half2*>(&pk.x) = __floats2half2_rn(o.x, o.y);
        *reinterpret_cast<__half2*>(&pk.y) = __floats2half2_rn(o.z, o.w);
        *((uint2*)&g_Hh[(size_t)w * DD] + lane) = pk;
    }
}

// -------- pair dot products (fp16 rows, fp32 accumulate) --------
__global__ void k_pairs(const int* __restrict__ pos, const int* __restrict__ neg,
                        float* __restrict__ out, int P) {
    int q = (blockIdx.x * blockDim.x + threadIdx.x) >> 5;
    int lane = threadIdx.x & 31;
    if (q >= 2 * P) return;
    const int* tab = (q < P) ? pos : neg;
    int p = (q < P) ? q : q - P;
    int a = tab[2 * p];
    int b = tab[2 * p + 1];
    uint2 ua = *((const uint2*)&g_Hh[(size_t)a * DD] + lane);
    uint2 ub = *((const uint2*)&g_Hh[(size_t)b * DD] + lane);
    float2 a0 = __half22float2(*reinterpret_cast<__half2*>(&ua.x));
    float2 a1 = __half22float2(*reinterpret_cast<__half2*>(&ua.y));
    float2 b0 = __half22float2(*reinterpret_cast<__half2*>(&ub.x));
    float2 b1 = __half22float2(*reinterpret_cast<__half2*>(&ub.y));
    float d = a0.x * b0.x + a0.y * b0.y + a1.x * b1.x + a1.y * b1.y;
    #pragma unroll
    for (int off = 16; off; off >>= 1) d += __shfl_xor_sync(0xffffffffu, d, off);
    if (lane == 0) out[q] = d;
}

extern "C" void kernel_launch(void* const* d_in, const int* in_sizes, int n_in,
                              void* d_out, int out_size) {
    const float* x   = (const float*)d_in[0];
    const float* W1  = (const float*)d_in[1];
    const float* b1  = (const float*)d_in[2];
    const float* W2  = (const float*)d_in[3];
    const float* b2  = (const float*)d_in[4];
    const int* ei    = (const int*)d_in[5];
    const int* edges = (const int*)d_in[6];
    const int* edneg = (const int*)d_in[7];
    float* out = (float*)d_out;

    int E = in_sizes[5] / 2;
    int P = in_sizes[6] / 2;
    const int* src = ei;
    const int* dst = ei + E;

    cudaFuncSetAttribute(k_gemm, cudaFuncAttributeMaxDynamicSharedMemorySize, GSMEM);

    void *pH = nullptr, *pSh = nullptr, *pWf1 = nullptr, *pWf2 = nullptr;
    cudaGetSymbolAddress(&pH, g_H);
    cudaGetSymbolAddress(&pSh, g_Sh);
    cudaGetSymbolAddress(&pWf1, g_Wf1);
    cudaGetSymbolAddress(&pWf2, g_Wf2);

    // W fragment pre-split + CSR build + dinv
    k_wsplit<<<(16 * 16 * 32 + 255) / 256, 256>>>(W1, (float4*)pWf1);
    k_wsplit<<<(16 * 16 * 32 + 255) / 256, 256>>>(W2, (float4*)pWf2);
    k_zero_counts<<<(NN + 255) / 256, 256>>>();
    k_degree<<<(E + 255) / 256, 256>>>(dst, E);
    k_scan1<<<NB_SCAN, 1024>>>(NN);
    k_scan2<<<1, 128>>>(NB_SCAN);
    k_scan3<<<(NN + 255) / 256, 256>>>(NN, E);
    k_bucket<<<(E + 255) / 256, 256>>>(src, dst, E);

    int gemm_blocks = (NN + 127) / 128;
    int gather_blocks = (NN * 32 + 255) / 256;

    // layer 1
    k_gemm<<<gemm_blocks, 1024, GSMEM>>>(x, (const float4*)pWf1, (__half*)pSh, NN);
    k_gather<true><<<gather_blocks, 256>>>(b1, NN);
    // layer 2
    k_gemm<<<gemm_blocks, 1024, GSMEM>>>((const float*)pH, (const float4*)pWf2, (__half*)pSh, NN);
    k_gather<false><<<gather_blocks, 256>>>(b2, NN);
    // link prediction
    int pair_blocks = (2 * P * 32 + 255) / 256;
    k_pairs<<<pair_blocks, 256>>>(edges, edneg, out, P);
}

// round 5
// speedup vs baseline: 1.4070x; 1.2051x over previous
#include <cuda_runtime.h>
#include <cuda_fp16.h>

#define NN 100000
#define EE_MAX 1600000
#define DD 128
#define NB_SCAN 98   // ceil(100000/1024)

// -------- scratch (device globals; no allocation allowed) --------
__device__ __half  g_Sh[(size_t)NN * DD];  // X@W, fp16 (scatter-read)
__device__ __half  g_Hh[(size_t)NN * DD];  // layer output, fp16 (GEMM2 input / pairs input)
__device__ float   g_dinv[NN];
__device__ int     g_count[NN];
__device__ int     g_rowptr[NN + 1];
__device__ int     g_cursor[NN];
__device__ int     g_col[EE_MAX];
__device__ int     g_bsum[NB_SCAN];
__device__ int     g_boff[NB_SCAN];
__device__ float4  g_Wf1[16 * 16 * 32];    // W in mma-fragment order (b0hi,b1hi,b0lo,b1lo)
__device__ float4  g_Wf2[16 * 16 * 32];

// -------- tf32 helpers --------
__device__ __forceinline__ unsigned f2tf(float x) {
    unsigned u;
    asm("cvt.rna.tf32.f32 %0, %1;" : "=r"(u) : "f"(x));
    return u;
}
__device__ __forceinline__ void split_tf32(float x, unsigned& hi, unsigned& lo) {
    hi = f2tf(x);
    float r = x - __uint_as_float(hi);
    lo = f2tf(r);
}
__device__ __forceinline__ void mma8(float* c, const unsigned* a, const unsigned* b) {
    asm volatile(
        "mma.sync.aligned.m16n8k8.row.col.f32.tf32.tf32.f32 "
        "{%0,%1,%2,%3}, {%4,%5,%6,%7}, {%8,%9}, {%0,%1,%2,%3};\n"
        : "+f"(c[0]), "+f"(c[1]), "+f"(c[2]), "+f"(c[3])
        : "r"(a[0]), "r"(a[1]), "r"(a[2]), "r"(a[3]), "r"(b[0]), "r"(b[1]));
}

// -------- CSR build --------
__global__ void k_zero_counts() {
    int i = blockIdx.x * blockDim.x + threadIdx.x;
    if (i < NN) g_count[i] = 0;
}

__global__ void k_degree(const int* __restrict__ dst, int E) {
    int e = blockIdx.x * blockDim.x + threadIdx.x;
    if (e < E) atomicAdd(&g_count[dst[e]], 1);
}

__global__ void k_scan1(int n) {
    __shared__ int s[1024];
    int i = blockIdx.x * 1024 + threadIdx.x;
    int v = (i < n) ? g_count[i] : 0;
    s[threadIdx.x] = v;
    __syncthreads();
    #pragma unroll
    for (int off = 1; off < 1024; off <<= 1) {
        int t = (threadIdx.x >= off) ? s[threadIdx.x - off] : 0;
        __syncthreads();
        s[threadIdx.x] += t;
        __syncthreads();
    }
    if (i < n) g_rowptr[i] = s[threadIdx.x] - v;  // exclusive within block
    if (threadIdx.x == 1023) g_bsum[blockIdx.x] = s[1023];
}

__global__ void k_scan2(int nb) {  // single block, 128 threads
    __shared__ int s[128];
    int t = threadIdx.x;
    int v = (t < nb) ? g_bsum[t] : 0;
    s[t] = v;
    __syncthreads();
    #pragma unroll
    for (int off = 1; off < 128; off <<= 1) {
        int tv = (t >= off) ? s[t - off] : 0;
        __syncthreads();
        s[t] += tv;
        __syncthreads();
    }
    if (t < nb) g_boff[t] = s[t] - v;  // exclusive
}

__global__ void k_scan3(int n, int E) {
    int i = blockIdx.x * blockDim.x + threadIdx.x;
    if (i < n) {
        int r = g_rowptr[i] + g_boff[i >> 10];
        g_rowptr[i] = r;
        g_cursor[i] = r;
        g_dinv[i]   = rsqrtf((float)g_count[i] + 1.0f);  // +1 self-loop
    }
    if (i == 0) g_rowptr[n] = E;
}

__global__ void k_bucket(const int* __restrict__ src, const int* __restrict__ dst, int E) {
    int e = blockIdx.x * blockDim.x + threadIdx.x;
    if (e < E) {
        int pos = atomicAdd(&g_cursor[dst[e]], 1);
        g_col[pos] = src[e];
    }
}

// -------- W -> fragment-order hi/lo split --------
__global__ void k_wsplit(const float* __restrict__ W, float4* __restrict__ out) {
    int i = blockIdx.x * blockDim.x + threadIdx.x;
    if (i >= 16 * 16 * 32) return;
    int lane = i & 31;
    int tile = i >> 5;
    int ntile = tile & 15;
    int kt = tile >> 4;
    int tig = lane & 3, g = lane >> 2;
    float b0 = W[(kt * 8 + tig) * DD + ntile * 8 + g];
    float b1 = W[(kt * 8 + tig + 4) * DD + ntile * 8 + g];
    unsigned b0h, b0l, b1h, b1l;
    split_tf32(b0, b0h, b0l);
    split_tf32(b1, b1h, b1l);
    out[i] = make_float4(__uint_as_float(b0h), __uint_as_float(b1h),
                         __uint_as_float(b0l), __uint_as_float(b1l));
}

// -------- GEMM (3xTF32 tensor core): Sh[n,128] = fp16( X[n,128] @ W ) --------
// IN = float (layer 1) or __half (layer 2).
#define GSMEM (128 * 132 * 4 + 16 * 16 * 32 * 16)   // 198656

template <typename IN>
__global__ void __launch_bounds__(1024, 1)
k_gemm(const IN* __restrict__ X, const float4* __restrict__ Wfrag,
       __half* __restrict__ out, int n) {
    extern __shared__ float sm[];
    float*  sX = sm;                          // 128 x 132 (padded)
    float4* sW = (float4*)(sm + 128 * 132);   // fragment float4s
    int t = threadIdx.x;
    int row0 = blockIdx.x * 128;

    #pragma unroll
    for (int j = t; j < 8192; j += 1024) sW[j] = Wfrag[j];
    #pragma unroll
    for (int j = t; j < 4096; j += 1024) {
        int r = j >> 5, c4 = j & 31;
        int gr = row0 + r;
        float4 v = make_float4(0.f, 0.f, 0.f, 0.f);
        if (gr < n) {
            if constexpr (sizeof(IN) == 4) {
                v = *(const float4*)&X[(size_t)gr * DD + c4 * 4];
            } else {
                uint2 u = *(const uint2*)&X[(size_t)gr * DD + c4 * 4];
                float2 f0 = __half22float2(*reinterpret_cast<__half2*>(&u.x));
                float2 f1 = __half22float2(*reinterpret_cast<__half2*>(&u.y));
                v = make_float4(f0.x, f0.y, f1.x, f1.y);
            }
        }
        *(float4*)&sX[r * 132 + c4 * 4] = v;
    }
    __syncthreads();

    int lane = t & 31, wid = t >> 5;
    int wr = wid >> 2, wc = wid & 3;
    int g = lane >> 2, tig = lane & 3;

    float c[4][4];
    #pragma unroll
    for (int i = 0; i < 4; i++)
        #pragma unroll
        for (int j = 0; j < 4; j++) c[i][j] = 0.f;

    const float* xb = &sX[(wr * 16 + g) * 132];

    #pragma unroll
    for (int kt = 0; kt < 16; kt++) {
        int k0 = kt * 8;
        float a0f = xb[k0 + tig];
        float a1f = xb[8 * 132 + k0 + tig];
        float a2f = xb[k0 + tig + 4];
        float a3f = xb[8 * 132 + k0 + tig + 4];
        unsigned ah[4], al[4];
        split_tf32(a0f, ah[0], al[0]);
        split_tf32(a1f, ah[1], al[1]);
        split_tf32(a2f, ah[2], al[2]);
        split_tf32(a3f, ah[3], al[3]);
        #pragma unroll
        for (int nt = 0; nt < 4; nt++) {
            float4 bf = sW[(kt * 16 + wc * 4 + nt) * 32 + lane];
            unsigned bh[2] = {__float_as_uint(bf.x), __float_as_uint(bf.y)};
            unsigned bl[2] = {__float_as_uint(bf.z), __float_as_uint(bf.w)};
            mma8(c[nt], ah, bh);   // hi*hi
            mma8(c[nt], al, bh);   // lo*hi
            mma8(c[nt], ah, bl);   // hi*lo
        }
    }

    int ra = row0 + wr * 16 + g;
    int rb = ra + 8;
    #pragma unroll
    for (int nt = 0; nt < 4; nt++) {
        int col = wc * 32 + nt * 8 + tig * 2;
        if (ra < n) *(__half2*)&out[(size_t)ra * DD + col] = __floats2half2_rn(c[nt][0], c[nt][1]);
        if (rb < n) *(__half2*)&out[(size_t)rb * DD + col] = __floats2half2_rn(c[nt][2], c[nt][3]);
    }
}

// -------- gather: half-warp (16 lanes) per node, uint4 (8 halves) per lane --------
// H[w,:] = act( dinv[w]*( dinv[w]*S[w,:] + sum_in dinv[s]*S[s,:] ) + b )
__device__ __forceinline__ void acc_h8(float* acc, uint4 u, float ds) {
    float2 f0 = __half22float2(*reinterpret_cast<__half2*>(&u.x));
    float2 f1 = __half22float2(*reinterpret_cast<__half2*>(&u.y));
    float2 f2 = __half22float2(*reinterpret_cast<__half2*>(&u.z));
    float2 f3 = __half22float2(*reinterpret_cast<__half2*>(&u.w));
    acc[0] = fmaf(ds, f0.x, acc[0]);
    acc[1] = fmaf(ds, f0.y, acc[1]);
    acc[2] = fmaf(ds, f1.x, acc[2]);
    acc[3] = fmaf(ds, f1.y, acc[3]);
    acc[4] = fmaf(ds, f2.x, acc[4]);
    acc[5] = fmaf(ds, f2.y, acc[5]);
    acc[6] = fmaf(ds, f3.x, acc[6]);
    acc[7] = fmaf(ds, f3.y, acc[7]);
}

template <bool RELU>
__global__ void k_gather(const float* __restrict__ bias, int n) {
    int w = (blockIdx.x * blockDim.x + threadIdx.x) >> 4;   // node = half-warp
    int lane = threadIdx.x & 15;                            // 16 lanes x 16B = 256B row
    if (w >= n) return;
    int beg = g_rowptr[w];
    int end = g_rowptr[w + 1];
    float dn = g_dinv[w];
    const uint4* selfp = (const uint4*)&g_Sh[(size_t)w * DD] + lane;
    float acc[8] = {0.f, 0.f, 0.f, 0.f, 0.f, 0.f, 0.f, 0.f};
    acc_h8(acc, __ldg(selfp), dn);  // self-loop
    int j = beg;
    for (; j + 4 <= end; j += 4) {
        int s0 = __ldg(&g_col[j]);
        int s1 = __ldg(&g_col[j + 1]);
        int s2 = __ldg(&g_col[j + 2]);
        int s3 = __ldg(&g_col[j + 3]);
        float d0 = __ldg(&g_dinv[s0]);
        float d1 = __ldg(&g_dinv[s1]);
        float d2 = __ldg(&g_dinv[s2]);
        float d3 = __ldg(&g_dinv[s3]);
        uint4 u0 = __ldg((const uint4*)&g_Sh[(size_t)s0 * DD] + lane);
        uint4 u1 = __ldg((const uint4*)&g_Sh[(size_t)s1 * DD] + lane);
        uint4 u2 = __ldg((const uint4*)&g_Sh[(size_t)s2 * DD] + lane);
        uint4 u3 = __ldg((const uint4*)&g_Sh[(size_t)s3 * DD] + lane);
        acc_h8(acc, u0, d0);
        acc_h8(acc, u1, d1);
        acc_h8(acc, u2, d2);
        acc_h8(acc, u3, d3);
    }
    for (; j < end; j++) {
        int s = __ldg(&g_col[j]);
        float ds = __ldg(&g_dinv[s]);
        acc_h8(acc, __ldg((const uint4*)&g_Sh[(size_t)s * DD] + lane), ds);
    }
    float4 b0 = *(const float4*)&bias[lane * 8];
    float4 b1 = *(const float4*)&bias[lane * 8 + 4];
    float o[8];
    o[0] = fmaf(acc[0], dn, b0.x); o[1] = fmaf(acc[1], dn, b0.y);
    o[2] = fmaf(acc[2], dn, b0.z); o[3] = fmaf(acc[3], dn, b0.w);
    o[4] = fmaf(acc[4], dn, b1.x); o[5] = fmaf(acc[5], dn, b1.y);
    o[6] = fmaf(acc[6], dn, b1.z); o[7] = fmaf(acc[7], dn, b1.w);
    if (RELU) {
        #pragma unroll
        for (int i = 0; i < 8; i++) o[i] = fmaxf(o[i], 0.f);
    }
    uint4 pk;
    *reinterpret_cast<__half2*>(&pk.x) = __floats2half2_rn(o[0], o[1]);
    *reinterpret_cast<__half2*>(&pk.y) = __floats2half2_rn(o[2], o[3]);
    *reinterpret_cast<__half2*>(&pk.z) = __floats2half2_rn(o[4], o[5]);
    *reinterpret_cast<__half2*>(&pk.w) = __floats2half2_rn(o[6], o[7]);
    *((uint4*)&g_Hh[(size_t)w * DD] + lane) = pk;
}

// -------- pair dot products: half-warp per pair, uint4 loads --------
__global__ void k_pairs(const int* __restrict__ pos, const int* __restrict__ neg,
                        float* __restrict__ out, int P) {
    int q = (blockIdx.x * blockDim.x + threadIdx.x) >> 4;
    int lane = threadIdx.x & 15;
    if (q >= 2 * P) return;
    const int* tab = (q < P) ? pos : neg;
    int p = (q < P) ? q : q - P;
    int a = __ldg(&tab[2 * p]);
    int b = __ldg(&tab[2 * p + 1]);
    uint4 ua = __ldg((const uint4*)&g_Hh[(size_t)a * DD] + lane);
    uint4 ub = __ldg((const uint4*)&g_Hh[(size_t)b * DD] + lane);
    float2 a0 = __half22float2(*reinterpret_cast<__half2*>(&ua.x));
    float2 a1 = __half22float2(*reinterpret_cast<__half2*>(&ua.y));
    float2 a2 = __half22float2(*reinterpret_cast<__half2*>(&ua.z));
    float2 a3 = __half22float2(*reinterpret_cast<__half2*>(&ua.w));
    float2 c0 = __half22float2(*reinterpret_cast<__half2*>(&ub.x));
    float2 c1 = __half22float2(*reinterpret_cast<__half2*>(&ub.y));
    float2 c2 = __half22float2(*reinterpret_cast<__half2*>(&ub.z));
    float2 c3 = __half22float2(*reinterpret_cast<__half2*>(&ub.w));
    float d = a0.x * c0.x + a0.y * c0.y + a1.x * c1.x + a1.y * c1.y
            + a2.x * c2.x + a2.y * c2.y + a3.x * c3.x + a3.y * c3.y;
    #pragma unroll
    for (int off = 8; off; off >>= 1) d += __shfl_xor_sync(0xffffffffu, d, off);
    if (lane == 0) out[q] = d;
}

extern "C" void kernel_launch(void* const* d_in, const int* in_sizes, int n_in,
                              void* d_out, int out_size) {
    const float* x   = (const float*)d_in[0];
    const float* W1  = (const float*)d_in[1];
    const float* b1  = (const float*)d_in[2];
    const float* W2  = (const float*)d_in[3];
    const float* b2  = (const float*)d_in[4];
    const int* ei    = (const int*)d_in[5];
    const int* edges = (const int*)d_in[6];
    const int* edneg = (const int*)d_in[7];
    float* out = (float*)d_out;

    int E = in_sizes[5] / 2;
    int P = in_sizes[6] / 2;
    const int* src = ei;
    const int* dst = ei + E;

    cudaFuncSetAttribute(k_gemm<float>, cudaFuncAttributeMaxDynamicSharedMemorySize, GSMEM);
    cudaFuncSetAttribute(k_gemm<__half>, cudaFuncAttributeMaxDynamicSharedMemorySize, GSMEM);

    void *pSh = nullptr, *pHh = nullptr, *pWf1 = nullptr, *pWf2 = nullptr;
    cudaGetSymbolAddress(&pSh, g_Sh);
    cudaGetSymbolAddress(&pHh, g_Hh);
    cudaGetSymbolAddress(&pWf1, g_Wf1);
    cudaGetSymbolAddress(&pWf2, g_Wf2);

    // W fragment pre-split + CSR build + dinv
    k_wsplit<<<(16 * 16 * 32 + 255) / 256, 256>>>(W1, (float4*)pWf1);
    k_wsplit<<<(16 * 16 * 32 + 255) / 256, 256>>>(W2, (float4*)pWf2);
    k_zero_counts<<<(NN + 255) / 256, 256>>>();
    k_degree<<<(E + 255) / 256, 256>>>(dst, E);
    k_scan1<<<NB_SCAN, 1024>>>(NN);
    k_scan2<<<1, 128>>>(NB_SCAN);
    k_scan3<<<(NN + 255) / 256, 256>>>(NN, E);
    k_bucket<<<(E + 255) / 256, 256>>>(src, dst, E);

    int gemm_blocks = (NN + 127) / 128;
    int gather_blocks = (NN * 16 + 255) / 256;

    // layer 1
    k_gemm<float><<<gemm_blocks, 1024, GSMEM>>>(x, (const float4*)pWf1, (__half*)pSh, NN);
    k_gather<true><<<gather_blocks, 256>>>(b1, NN);
    // layer 2
    k_gemm<__half><<<gemm_blocks, 1024, GSMEM>>>((const __half*)pHh, (const float4*)pWf2, (__half*)pSh, NN);
    k_gather<false><<<gather_blocks, 256>>>(b2, NN);
    // link prediction
    int pair_blocks = (2 * P * 16 + 255) / 256;
    k_pairs<<<pair_blocks, 256>>>(edges, edneg, out, P);
}

// round 6
// speedup vs baseline: 1.6562x; 1.1771x over previous
#include <cuda_runtime.h>
#include <cuda_fp16.h>

#define NN 100000
#define EE_MAX 1600000
#define DD 128
#define NB_SCAN 98   // ceil(100000/1024)

// -------- scratch (device globals; no allocation allowed) --------
__device__ __half  g_Sh[(size_t)NN * DD];  // X@W, fp16 (scatter-read)
__device__ __half  g_Hh[(size_t)NN * DD];  // layer output, fp16 (GEMM2 input / pairs input)
__device__ float   g_dinv[NN];
__device__ int     g_count[NN];
__device__ int     g_rowptr[NN + 1];
__device__ int     g_cursor[NN];
__device__ int     g_col[EE_MAX];
__device__ int     g_bsum[NB_SCAN];
__device__ int     g_boff[NB_SCAN];
// W in fp16 hi/lo mma-fragment order: per (kt,ntg,lane) uint4 {b0hi2,b1hi2,b0lo2,b1lo2}
__device__ uint4   g_Wf1[8 * 16 * 32];
__device__ uint4   g_Wf2[8 * 16 * 32];

__device__ __forceinline__ unsigned packh2(__half a, __half b) {
    __half2 h = __halves2half2(a, b);
    return *reinterpret_cast<unsigned*>(&h);
}

__device__ __forceinline__ void mma16(float* c, const unsigned* a, const unsigned* b) {
    asm volatile(
        "mma.sync.aligned.m16n8k16.row.col.f32.f16.f16.f32 "
        "{%0,%1,%2,%3}, {%4,%5,%6,%7}, {%8,%9}, {%0,%1,%2,%3};\n"
        : "+f"(c[0]), "+f"(c[1]), "+f"(c[2]), "+f"(c[3])
        : "r"(a[0]), "r"(a[1]), "r"(a[2]), "r"(a[3]), "r"(b[0]), "r"(b[1]));
}

// -------- CSR build --------
__global__ void k_degree(const int* __restrict__ dst, int E) {
    int e = blockIdx.x * blockDim.x + threadIdx.x;
    if (e < E) atomicAdd(&g_count[dst[e]], 1);
}

__global__ void k_scan1(int n) {
    __shared__ int s[1024];
    int i = blockIdx.x * 1024 + threadIdx.x;
    int v = (i < n) ? g_count[i] : 0;
    s[threadIdx.x] = v;
    __syncthreads();
    #pragma unroll
    for (int off = 1; off < 1024; off <<= 1) {
        int t = (threadIdx.x >= off) ? s[threadIdx.x - off] : 0;
        __syncthreads();
        s[threadIdx.x] += t;
        __syncthreads();
    }
    if (i < n) g_rowptr[i] = s[threadIdx.x] - v;  // exclusive within block
    if (threadIdx.x == 1023) g_bsum[blockIdx.x] = s[1023];
}

__global__ void k_scan2(int nb) {  // single block, 128 threads
    __shared__ int s[128];
    int t = threadIdx.x;
    int v = (t < nb) ? g_bsum[t] : 0;
    s[t] = v;
    __syncthreads();
    #pragma unroll
    for (int off = 1; off < 128; off <<= 1) {
        int tv = (t >= off) ? s[t - off] : 0;
        __syncthreads();
        s[t] += tv;
        __syncthreads();
    }
    if (t < nb) g_boff[t] = s[t] - v;  // exclusive
}

__global__ void k_scan3(int n, int E) {
    int i = blockIdx.x * blockDim.x + threadIdx.x;
    if (i < n) {
        int r = g_rowptr[i] + g_boff[i >> 10];
        g_rowptr[i] = r;
        g_cursor[i] = r;
        g_dinv[i]   = rsqrtf((float)g_count[i] + 1.0f);  // +1 self-loop
    }
    if (i == 0) g_rowptr[n] = E;
}

__global__ void k_bucket(const int* __restrict__ src, const int* __restrict__ dst, int E) {
    int e = blockIdx.x * blockDim.x + threadIdx.x;
    if (e < E) {
        int pos = atomicAdd(&g_cursor[dst[e]], 1);
        g_col[pos] = src[e];
    }
}

// -------- W -> fp16 hi/lo fragment split (m16n8k16 B layout) --------
__global__ void k_wsplit(const float* __restrict__ W, uint4* __restrict__ out) {
    int i = blockIdx.x * blockDim.x + threadIdx.x;
    if (i >= 8 * 16 * 32) return;
    int lane = i & 31;
    int tile = i >> 5;
    int ntg = tile & 15;
    int kt = tile >> 4;
    int tig = lane & 3, g = lane >> 2;
    int k0 = kt * 16, n0 = ntg * 8;
    float w00 = W[(k0 + 2 * tig) * DD + n0 + g];
    float w01 = W[(k0 + 2 * tig + 1) * DD + n0 + g];
    float w10 = W[(k0 + 2 * tig + 8) * DD + n0 + g];
    float w11 = W[(k0 + 2 * tig + 9) * DD + n0 + g];
    __half h00 = __float2half_rn(w00), h01 = __float2half_rn(w01);
    __half h10 = __float2half_rn(w10), h11 = __float2half_rn(w11);
    __half l00 = __float2half_rn(w00 - __half2float(h00));
    __half l01 = __float2half_rn(w01 - __half2float(h01));
    __half l10 = __float2half_rn(w10 - __half2float(h10));
    __half l11 = __float2half_rn(w11 - __half2float(h11));
    uint4 o;
    o.x = packh2(h00, h01);   // b0 hi
    o.y = packh2(h10, h11);   // b1 hi
    o.z = packh2(l00, l01);   // b0 lo
    o.w = packh2(l10, l11);   // b1 lo
    out[i] = o;
}

// -------- GEMM (split-fp16 tensor core): Sh[n,128] = fp16( X[n,128] @ W ) --------
// SPLIT_A: true for fp32 input (layer 1; 3 mma), false for fp16-exact input (layer 2; 2 mma)
#define GSMEM (128 * 132 * 4 + 8 * 16 * 32 * 16)   // 67584 + 65536 = 133120

template <typename IN, bool SPLIT_A>
__global__ void __launch_bounds__(1024, 1)
k_gemm(const IN* __restrict__ X, const uint4* __restrict__ Wfrag,
       __half* __restrict__ out, int n) {
    extern __shared__ float sm[];
    float* sX = sm;                         // 128 x 132 (padded) fp32
    uint4* sW = (uint4*)(sm + 128 * 132);   // 8*16*32 fragment uint4s
    int t = threadIdx.x;
    int row0 = blockIdx.x * 128;

    #pragma unroll
    for (int j = t; j < 4096; j += 1024) sW[j] = Wfrag[j];
    #pragma unroll
    for (int j = t; j < 4096; j += 1024) {
        int r = j >> 5, c4 = j & 31;
        int gr = row0 + r;
        float4 v = make_float4(0.f, 0.f, 0.f, 0.f);
        if (gr < n) {
            if constexpr (sizeof(IN) == 4) {
                v = *(const float4*)&X[(size_t)gr * DD + c4 * 4];
            } else {
                uint2 u = *(const uint2*)&X[(size_t)gr * DD + c4 * 4];
                float2 f0 = __half22float2(*reinterpret_cast<__half2*>(&u.x));
                float2 f1 = __half22float2(*reinterpret_cast<__half2*>(&u.y));
                v = make_float4(f0.x, f0.y, f1.x, f1.y);
            }
        }
        *(float4*)&sX[r * 132 + c4 * 4] = v;
    }
    __syncthreads();

    int lane = t & 31, wid = t >> 5;
    int wr = wid >> 2, wc = wid & 3;
    int g = lane >> 2, tig = lane & 3;

    float c[4][4];
    #pragma unroll
    for (int i = 0; i < 4; i++)
        #pragma unroll
        for (int j = 0; j < 4; j++) c[i][j] = 0.f;

    const float* xb = &sX[(wr * 16 + g) * 132];

    #pragma unroll
    for (int kt = 0; kt < 8; kt++) {
        int k0 = kt * 16;
        // A fragments (m16k16 row-major): pairs of adjacent k
        float2 p0 = *(const float2*)&xb[k0 + 2 * tig];            // row g,  k 2tig..+1
        float2 p1 = *(const float2*)&xb[8 * 132 + k0 + 2 * tig];  // row g+8
        float2 p2 = *(const float2*)&xb[k0 + 2 * tig + 8];        // row g,  k 2tig+8..+9
        float2 p3 = *(const float2*)&xb[8 * 132 + k0 + 2 * tig + 8];
        __half h00 = __float2half_rn(p0.x), h01 = __float2half_rn(p0.y);
        __half h10 = __float2half_rn(p1.x), h11 = __float2half_rn(p1.y);
        __half h20 = __float2half_rn(p2.x), h21 = __float2half_rn(p2.y);
        __half h30 = __float2half_rn(p3.x), h31 = __float2half_rn(p3.y);
        unsigned ah[4], al[4];
        ah[0] = packh2(h00, h01);
        ah[1] = packh2(h10, h11);
        ah[2] = packh2(h20, h21);
        ah[3] = packh2(h30, h31);
        if constexpr (SPLIT_A) {
            al[0] = packh2(__float2half_rn(p0.x - __half2float(h00)),
                           __float2half_rn(p0.y - __half2float(h01)));
            al[1] = packh2(__float2half_rn(p1.x - __half2float(h10)),
                           __float2half_rn(p1.y - __half2float(h11)));
            al[2] = packh2(__float2half_rn(p2.x - __half2float(h20)),
                           __float2half_rn(p2.y - __half2float(h21)));
            al[3] = packh2(__float2half_rn(p3.x - __half2float(h30)),
                           __float2half_rn(p3.y - __half2float(h31)));
        }
        #pragma unroll
        for (int nt = 0; nt < 4; nt++) {
            uint4 bf = sW[(kt * 16 + wc * 4 + nt) * 32 + lane];
            unsigned bh[2] = {bf.x, bf.y};
            unsigned bl[2] = {bf.z, bf.w};
            mma16(c[nt], ah, bh);                       // hi*hi
            if constexpr (SPLIT_A) mma16(c[nt], al, bh);  // lo*hi
            mma16(c[nt], ah, bl);                       // hi*lo
        }
    }

    int ra = row0 + wr * 16 + g;
    int rb = ra + 8;
    #pragma unroll
    for (int nt = 0; nt < 4; nt++) {
        int col = wc * 32 + nt * 8 + tig * 2;
        if (ra < n) *(__half2*)&out[(size_t)ra * DD + col] = __floats2half2_rn(c[nt][0], c[nt][1]);
        if (rb < n) *(__half2*)&out[(size_t)rb * DD + col] = __floats2half2_rn(c[nt][2], c[nt][3]);
    }
}

// -------- gather: half-warp (16 lanes) per node, uint4 (8 halves) per lane --------
// H[w,:] = act( dinv[w]*( dinv[w]*S[w,:] + sum_in dinv[s]*S[s,:] ) + b )
__device__ __forceinline__ void acc_h8(float* acc, uint4 u, float ds) {
    float2 f0 = __half22float2(*reinterpret_cast<__half2*>(&u.x));
    float2 f1 = __half22float2(*reinterpret_cast<__half2*>(&u.y));
    float2 f2 = __half22float2(*reinterpret_cast<__half2*>(&u.z));
    float2 f3 = __half22float2(*reinterpret_cast<__half2*>(&u.w));
    acc[0] = fmaf(ds, f0.x, acc[0]);
    acc[1] = fmaf(ds, f0.y, acc[1]);
    acc[2] = fmaf(ds, f1.x, acc[2]);
    acc[3] = fmaf(ds, f1.y, acc[3]);
    acc[4] = fmaf(ds, f2.x, acc[4]);
    acc[5] = fmaf(ds, f2.y, acc[5]);
    acc[6] = fmaf(ds, f3.x, acc[6]);
    acc[7] = fmaf(ds, f3.y, acc[7]);
}

template <bool RELU>
__global__ void k_gather(const float* __restrict__ bias, int n) {
    int w = (blockIdx.x * blockDim.x + threadIdx.x) >> 4;   // node = half-warp
    int lane = threadIdx.x & 15;                            // 16 lanes x 16B = 256B row
    if (w >= n) return;
    int beg = g_rowptr[w];
    int end = g_rowptr[w + 1];
    float dn = g_dinv[w];
    const uint4* selfp = (const uint4*)&g_Sh[(size_t)w * DD] + lane;
    float acc[8] = {0.f, 0.f, 0.f, 0.f, 0.f, 0.f, 0.f, 0.f};
    acc_h8(acc, __ldg(selfp), dn);  // self-loop
    int j = beg;
    for (; j + 4 <= end; j += 4) {
        int s0 = __ldg(&g_col[j]);
        int s1 = __ldg(&g_col[j + 1]);
        int s2 = __ldg(&g_col[j + 2]);
        int s3 = __ldg(&g_col[j + 3]);
        float d0 = __ldg(&g_dinv[s0]);
        float d1 = __ldg(&g_dinv[s1]);
        float d2 = __ldg(&g_dinv[s2]);
        float d3 = __ldg(&g_dinv[s3]);
        uint4 u0 = __ldg((const uint4*)&g_Sh[(size_t)s0 * DD] + lane);
        uint4 u1 = __ldg((const uint4*)&g_Sh[(size_t)s1 * DD] + lane);
        uint4 u2 = __ldg((const uint4*)&g_Sh[(size_t)s2 * DD] + lane);
        uint4 u3 = __ldg((const uint4*)&g_Sh[(size_t)s3 * DD] + lane);
        acc_h8(acc, u0, d0);
        acc_h8(acc, u1, d1);
        acc_h8(acc, u2, d2);
        acc_h8(acc, u3, d3);
    }
    for (; j < end; j++) {
        int s = __ldg(&g_col[j]);
        float ds = __ldg(&g_dinv[s]);
        acc_h8(acc, __ldg((const uint4*)&g_Sh[(size_t)s * DD] + lane), ds);
    }
    float4 b0 = *(const float4*)&bias[lane * 8];
    float4 b1 = *(const float4*)&bias[lane * 8 + 4];
    float o[8];
    o[0] = fmaf(acc[0], dn, b0.x); o[1] = fmaf(acc[1], dn, b0.y);
    o[2] = fmaf(acc[2], dn, b0.z); o[3] = fmaf(acc[3], dn, b0.w);
    o[4] = fmaf(acc[4], dn, b1.x); o[5] = fmaf(acc[5], dn, b1.y);
    o[6] = fmaf(acc[6], dn, b1.z); o[7] = fmaf(acc[7], dn, b1.w);
    if (RELU) {
        #pragma unroll
        for (int i = 0; i < 8; i++) o[i] = fmaxf(o[i], 0.f);
    }
    uint4 pk;
    *reinterpret_cast<__half2*>(&pk.x) = __floats2half2_rn(o[0], o[1]);
    *reinterpret_cast<__half2*>(&pk.y) = __floats2half2_rn(o[2], o[3]);
    *reinterpret_cast<__half2*>(&pk.z) = __floats2half2_rn(o[4], o[5]);
    *reinterpret_cast<__half2*>(&pk.w) = __floats2half2_rn(o[6], o[7]);
    *((uint4*)&g_Hh[(size_t)w * DD] + lane) = pk;
}

// -------- pair dot products: half-warp per pair, uint4 loads --------
__global__ void k_pairs(const int* __restrict__ pos, const int* __restrict__ neg,
                        float* __restrict__ out, int P) {
    int q = (blockIdx.x * blockDim.x + threadIdx.x) >> 4;
    int lane = threadIdx.x & 15;
    if (q >= 2 * P) return;
    const int* tab = (q < P) ? pos : neg;
    int p = (q < P) ? q : q - P;
    int a = __ldg(&tab[2 * p]);
    int b = __ldg(&tab[2 * p + 1]);
    uint4 ua = __ldg((const uint4*)&g_Hh[(size_t)a * DD] + lane);
    uint4 ub = __ldg((const uint4*)&g_Hh[(size_t)b * DD] + lane);
    float2 a0 = __half22float2(*reinterpret_cast<__half2*>(&ua.x));
    float2 a1 = __half22float2(*reinterpret_cast<__half2*>(&ua.y));
    float2 a2 = __half22float2(*reinterpret_cast<__half2*>(&ua.z));
    float2 a3 = __half22float2(*reinterpret_cast<__half2*>(&ua.w));
    float2 c0 = __half22float2(*reinterpret_cast<__half2*>(&ub.x));
    float2 c1 = __half22float2(*reinterpret_cast<__half2*>(&ub.y));
    float2 c2 = __half22float2(*reinterpret_cast<__half2*>(&ub.z));
    float2 c3 = __half22float2(*reinterpret_cast<__half2*>(&ub.w));
    float d = a0.x * c0.x + a0.y * c0.y + a1.x * c1.x + a1.y * c1.y
            + a2.x * c2.x + a2.y * c2.y + a3.x * c3.x + a3.y * c3.y;
    #pragma unroll
    for (int off = 8; off; off >>= 1) d += __shfl_xor_sync(0xffffffffu, d, off);
    if (lane == 0) out[q] = d;
}

extern "C" void kernel_launch(void* const* d_in, const int* in_sizes, int n_in,
                              void* d_out, int out_size) {
    const float* x   = (const float*)d_in[0];
    const float* W1  = (const float*)d_in[1];
    const float* b1  = (const float*)d_in[2];
    const float* W2  = (const float*)d_in[3];
    const float* b2  = (const float*)d_in[4];
    const int* ei    = (const int*)d_in[5];
    const int* edges = (const int*)d_in[6];
    const int* edneg = (const int*)d_in[7];
    float* out = (float*)d_out;

    int E = in_sizes[5] / 2;
    int P = in_sizes[6] / 2;
    const int* src = ei;
    const int* dst = ei + E;

    cudaFuncSetAttribute(k_gemm<float, true>, cudaFuncAttributeMaxDynamicSharedMemorySize, GSMEM);
    cudaFuncSetAttribute(k_gemm<__half, false>, cudaFuncAttributeMaxDynamicSharedMemorySize, GSMEM);

    void *pSh = nullptr, *pHh = nullptr, *pWf1 = nullptr, *pWf2 = nullptr, *pCnt = nullptr;
    cudaGetSymbolAddress(&pSh, g_Sh);
    cudaGetSymbolAddress(&pHh, g_Hh);
    cudaGetSymbolAddress(&pWf1, g_Wf1);
    cudaGetSymbolAddress(&pWf2, g_Wf2);
    cudaGetSymbolAddress(&pCnt, g_count);

    // W fragment pre-split + CSR build + dinv
    k_wsplit<<<(8 * 16 * 32 + 255) / 256, 256>>>(W1, (uint4*)pWf1);
    k_wsplit<<<(8 * 16 * 32 + 255) / 256, 256>>>(W2, (uint4*)pWf2);
    cudaMemsetAsync(pCnt, 0, NN * sizeof(int));
    k_degree<<<(E + 255) / 256, 256>>>(dst, E);
    k_scan1<<<NB_SCAN, 1024>>>(NN);
    k_scan2<<<1, 128>>>(NB_SCAN);
    k_scan3<<<(NN + 255) / 256, 256>>>(NN, E);
    k_bucket<<<(E + 255) / 256, 256>>>(src, dst, E);

    int gemm_blocks = (NN + 127) / 128;
    int gather_blocks = (NN * 16 + 255) / 256;

    // layer 1
    k_gemm<float, true><<<gemm_blocks, 1024, GSMEM>>>(x, (const uint4*)pWf1, (__half*)pSh, NN);
    k_gather<true><<<gather_blocks, 256>>>(b1, NN);
    // layer 2
    k_gemm<__half, false><<<gemm_blocks, 1024, GSMEM>>>((const __half*)pHh, (const uint4*)pWf2, (__half*)pSh, NN);
    k_gather<false><<<gather_blocks, 256>>>(b2, NN);
    // link prediction
    int pair_blocks = (2 * P * 16 + 255) / 256;
    k_pairs<<<pair_blocks, 256>>>(edges, edneg, out, P);
}

// round 7
// speedup vs baseline: 1.7698x; 1.0686x over previous
#include <cuda_runtime.h>
#include <cuda_fp16.h>

#define NN 100000
#define EE_MAX 1600000
#define DD 128
#define NB_SCAN 98   // ceil(100000/1024)

// -------- scratch (device globals; no allocation allowed) --------
__device__ __half  g_Sh[(size_t)NN * DD];  // X@W (prescaled by dinv), fp16
__device__ __half  g_Hh[(size_t)NN * DD];  // layer output, fp16
__device__ float   g_dinv[NN];
__device__ int     g_count[NN];
__device__ int     g_rowptr[NN + 1];
__device__ int     g_cursor[NN];
__device__ int     g_col[EE_MAX];
__device__ int     g_bsum[NB_SCAN];
__device__ int     g_boff[NB_SCAN];
// W in fp16 hi/lo mma-fragment order: per (kt,ntg,lane) uint4 {b0hi2,b1hi2,b0lo2,b1lo2}
__device__ uint4   g_Wf1[8 * 16 * 32];
__device__ uint4   g_Wf2[8 * 16 * 32];

__device__ __forceinline__ unsigned packh2(__half a, __half b) {
    __half2 h = __halves2half2(a, b);
    return *reinterpret_cast<unsigned*>(&h);
}

__device__ __forceinline__ void mma16(float* c, const unsigned* a, const unsigned* b) {
    asm volatile(
        "mma.sync.aligned.m16n8k16.row.col.f32.f16.f16.f32 "
        "{%0,%1,%2,%3}, {%4,%5,%6,%7}, {%8,%9}, {%0,%1,%2,%3};\n"
        : "+f"(c[0]), "+f"(c[1]), "+f"(c[2]), "+f"(c[3])
        : "r"(a[0]), "r"(a[1]), "r"(a[2]), "r"(a[3]), "r"(b[0]), "r"(b[1]));
}

// -------- CSR build --------
__global__ void k_degree(const int* __restrict__ dst, int E) {
    int i = blockIdx.x * blockDim.x + threadIdx.x;
    int e = i * 4;
    if (e + 4 <= E) {
        int4 d = *(const int4*)&dst[e];
        atomicAdd(&g_count[d.x], 1);
        atomicAdd(&g_count[d.y], 1);
        atomicAdd(&g_count[d.z], 1);
        atomicAdd(&g_count[d.w], 1);
    } else {
        for (; e < E; e++) atomicAdd(&g_count[dst[e]], 1);
    }
}

__global__ void k_scan1(int n) {
    __shared__ int s[1024];
    int i = blockIdx.x * 1024 + threadIdx.x;
    int v = (i < n) ? g_count[i] : 0;
    s[threadIdx.x] = v;
    __syncthreads();
    #pragma unroll
    for (int off = 1; off < 1024; off <<= 1) {
        int t = (threadIdx.x >= off) ? s[threadIdx.x - off] : 0;
        __syncthreads();
        s[threadIdx.x] += t;
        __syncthreads();
    }
    if (i < n) g_rowptr[i] = s[threadIdx.x] - v;  // exclusive within block
    if (threadIdx.x == 1023) g_bsum[blockIdx.x] = s[1023];
}

__global__ void k_scan2(int nb) {  // single block, 128 threads
    __shared__ int s[128];
    int t = threadIdx.x;
    int v = (t < nb) ? g_bsum[t] : 0;
    s[t] = v;
    __syncthreads();
    #pragma unroll
    for (int off = 1; off < 128; off <<= 1) {
        int tv = (t >= off) ? s[t - off] : 0;
        __syncthreads();
        s[t] += tv;
        __syncthreads();
    }
    if (t < nb) g_boff[t] = s[t] - v;  // exclusive
}

__global__ void k_scan3(int n, int E) {
    int i = blockIdx.x * blockDim.x + threadIdx.x;
    if (i < n) {
        int r = g_rowptr[i] + g_boff[i >> 10];
        g_rowptr[i] = r;
        g_cursor[i] = r;
        g_dinv[i]   = rsqrtf((float)g_count[i] + 1.0f);  // +1 self-loop
    }
    if (i == 0) g_rowptr[n] = E;
}

__global__ void k_bucket(const int* __restrict__ src, const int* __restrict__ dst, int E) {
    int i = blockIdx.x * blockDim.x + threadIdx.x;
    int e = i * 2;
    if (e + 2 <= E) {
        int2 s = *(const int2*)&src[e];
        int2 d = *(const int2*)&dst[e];
        int p0 = atomicAdd(&g_cursor[d.x], 1);
        g_col[p0] = s.x;
        int p1 = atomicAdd(&g_cursor[d.y], 1);
        g_col[p1] = s.y;
    } else {
        for (; e < E; e++) {
            int pos = atomicAdd(&g_cursor[dst[e]], 1);
            g_col[pos] = src[e];
        }
    }
}

// -------- W -> fp16 hi/lo fragment split (m16n8k16 B layout) --------
__global__ void k_wsplit(const float* __restrict__ W, uint4* __restrict__ out) {
    int i = blockIdx.x * blockDim.x + threadIdx.x;
    if (i >= 8 * 16 * 32) return;
    int lane = i & 31;
    int tile = i >> 5;
    int ntg = tile & 15;
    int kt = tile >> 4;
    int tig = lane & 3, g = lane >> 2;
    int k0 = kt * 16, n0 = ntg * 8;
    float w00 = W[(k0 + 2 * tig) * DD + n0 + g];
    float w01 = W[(k0 + 2 * tig + 1) * DD + n0 + g];
    float w10 = W[(k0 + 2 * tig + 8) * DD + n0 + g];
    float w11 = W[(k0 + 2 * tig + 9) * DD + n0 + g];
    __half h00 = __float2half_rn(w00), h01 = __float2half_rn(w01);
    __half h10 = __float2half_rn(w10), h11 = __float2half_rn(w11);
    __half l00 = __float2half_rn(w00 - __half2float(h00));
    __half l01 = __float2half_rn(w01 - __half2float(h01));
    __half l10 = __float2half_rn(w10 - __half2float(h10));
    __half l11 = __float2half_rn(w11 - __half2float(h11));
    uint4 o;
    o.x = packh2(h00, h01);
    o.y = packh2(h10, h11);
    o.z = packh2(l00, l01);
    o.w = packh2(l10, l11);
    out[i] = o;
}

// -------- GEMM (split-fp16 tensor core) --------
// SPLIT_A: fp32 input (layer 1; 3 mma) vs fp16-exact input (layer 2; 2 mma)
// SCALE:   multiply output row by dinv[row] in epilogue (layer 2)
#define GSMEM (128 * 132 * 4 + 8 * 16 * 32 * 16)   // 133120

template <typename IN, bool SPLIT_A, bool SCALE>
__global__ void __launch_bounds__(1024, 1)
k_gemm(const IN* __restrict__ X, const uint4* __restrict__ Wfrag,
       __half* __restrict__ out, int n) {
    extern __shared__ float sm[];
    float* sX = sm;                         // 128 x 132 (padded) fp32
    uint4* sW = (uint4*)(sm + 128 * 132);   // 8*16*32 fragment uint4s
    int t = threadIdx.x;
    int row0 = blockIdx.x * 128;

    #pragma unroll
    for (int j = t; j < 4096; j += 1024) sW[j] = Wfrag[j];
    #pragma unroll
    for (int j = t; j < 4096; j += 1024) {
        int r = j >> 5, c4 = j & 31;
        int gr = row0 + r;
        float4 v = make_float4(0.f, 0.f, 0.f, 0.f);
        if (gr < n) {
            if constexpr (sizeof(IN) == 4) {
                v = *(const float4*)&X[(size_t)gr * DD + c4 * 4];
            } else {
                uint2 u = *(const uint2*)&X[(size_t)gr * DD + c4 * 4];
                float2 f0 = __half22float2(*reinterpret_cast<__half2*>(&u.x));
                float2 f1 = __half22float2(*reinterpret_cast<__half2*>(&u.y));
                v = make_float4(f0.x, f0.y, f1.x, f1.y);
            }
        }
        *(float4*)&sX[r * 132 + c4 * 4] = v;
    }
    __syncthreads();

    int lane = t & 31, wid = t >> 5;
    int wr = wid >> 2, wc = wid & 3;
    int g = lane >> 2, tig = lane & 3;

    float c[4][4];
    #pragma unroll
    for (int i = 0; i < 4; i++)
        #pragma unroll
        for (int j = 0; j < 4; j++) c[i][j] = 0.f;

    const float* xb = &sX[(wr * 16 + g) * 132];

    #pragma unroll
    for (int kt = 0; kt < 8; kt++) {
        int k0 = kt * 16;
        float2 p0 = *(const float2*)&xb[k0 + 2 * tig];
        float2 p1 = *(const float2*)&xb[8 * 132 + k0 + 2 * tig];
        float2 p2 = *(const float2*)&xb[k0 + 2 * tig + 8];
        float2 p3 = *(const float2*)&xb[8 * 132 + k0 + 2 * tig + 8];
        __half h00 = __float2half_rn(p0.x), h01 = __float2half_rn(p0.y);
        __half h10 = __float2half_rn(p1.x), h11 = __float2half_rn(p1.y);
        __half h20 = __float2half_rn(p2.x), h21 = __float2half_rn(p2.y);
        __half h30 = __float2half_rn(p3.x), h31 = __float2half_rn(p3.y);
        unsigned ah[4], al[4];
        ah[0] = packh2(h00, h01);
        ah[1] = packh2(h10, h11);
        ah[2] = packh2(h20, h21);
        ah[3] = packh2(h30, h31);
        if constexpr (SPLIT_A) {
            al[0] = packh2(__float2half_rn(p0.x - __half2float(h00)),
                           __float2half_rn(p0.y - __half2float(h01)));
            al[1] = packh2(__float2half_rn(p1.x - __half2float(h10)),
                           __float2half_rn(p1.y - __half2float(h11)));
            al[2] = packh2(__float2half_rn(p2.x - __half2float(h20)),
                           __float2half_rn(p2.y - __half2float(h21)));
            al[3] = packh2(__float2half_rn(p3.x - __half2float(h30)),
                           __float2half_rn(p3.y - __half2float(h31)));
        }
        #pragma unroll
        for (int nt = 0; nt < 4; nt++) {
            uint4 bf = sW[(kt * 16 + wc * 4 + nt) * 32 + lane];
            unsigned bh[2] = {bf.x, bf.y};
            unsigned bl[2] = {bf.z, bf.w};
            mma16(c[nt], ah, bh);
            if constexpr (SPLIT_A) mma16(c[nt], al, bh);
            mma16(c[nt], ah, bl);
        }
    }

    int ra = row0 + wr * 16 + g;
    int rb = ra + 8;
    float sa = 1.f, sb = 1.f;
    if constexpr (SCALE) {
        if (ra < n) sa = g_dinv[ra];
        if (rb < n) sb = g_dinv[rb];
    }
    #pragma unroll
    for (int nt = 0; nt < 4; nt++) {
        int col = wc * 32 + nt * 8 + tig * 2;
        if (ra < n) *(__half2*)&out[(size_t)ra * DD + col] =
            __floats2half2_rn(c[nt][0] * sa, c[nt][1] * sa);
        if (rb < n) *(__half2*)&out[(size_t)rb * DD + col] =
            __floats2half2_rn(c[nt][2] * sb, c[nt][3] * sb);
    }
}

// -------- prescale Sh rows by dinv (layer 1 only; after CSR join) --------
__global__ void k_scale(int n) {
    int i = blockIdx.x * blockDim.x + threadIdx.x;   // one uint4 = 8 halves
    if (i >= n * 16) return;
    int node = i >> 4;
    float d = g_dinv[node];
    uint4 u = *((uint4*)g_Sh + i);
    float2 f0 = __half22float2(*reinterpret_cast<__half2*>(&u.x));
    float2 f1 = __half22float2(*reinterpret_cast<__half2*>(&u.y));
    float2 f2 = __half22float2(*reinterpret_cast<__half2*>(&u.z));
    float2 f3 = __half22float2(*reinterpret_cast<__half2*>(&u.w));
    uint4 o;
    *reinterpret_cast<__half2*>(&o.x) = __floats2half2_rn(f0.x * d, f0.y * d);
    *reinterpret_cast<__half2*>(&o.y) = __floats2half2_rn(f1.x * d, f1.y * d);
    *reinterpret_cast<__half2*>(&o.z) = __floats2half2_rn(f2.x * d, f2.y * d);
    *reinterpret_cast<__half2*>(&o.w) = __floats2half2_rn(f3.x * d, f3.y * d);
    *((uint4*)g_Sh + i) = o;
}

// -------- gather over prescaled rows: H[w] = act( dinv[w]*Σ_{s∈N(w)∪{w}} Sh[s] + b ) ----
__device__ __forceinline__ void add_h8(float* acc, uint4 u) {
    float2 f0 = __half22float2(*reinterpret_cast<__half2*>(&u.x));
    float2 f1 = __half22float2(*reinterpret_cast<__half2*>(&u.y));
    float2 f2 = __half22float2(*reinterpret_cast<__half2*>(&u.z));
    float2 f3 = __half22float2(*reinterpret_cast<__half2*>(&u.w));
    acc[0] += f0.x; acc[1] += f0.y;
    acc[2] += f1.x; acc[3] += f1.y;
    acc[4] += f2.x; acc[5] += f2.y;
    acc[6] += f3.x; acc[7] += f3.y;
}

template <bool RELU>
__global__ void k_gather(const float* __restrict__ bias, int n) {
    int w = (blockIdx.x * blockDim.x + threadIdx.x) >> 4;   // node = half-warp
    int lane = threadIdx.x & 15;                            // 16 lanes x 16B = 256B row
    if (w >= n) return;
    int beg = g_rowptr[w];
    int end = g_rowptr[w + 1];
    float dn = g_dinv[w];
    float acc[8] = {0.f, 0.f, 0.f, 0.f, 0.f, 0.f, 0.f, 0.f};
    add_h8(acc, __ldg((const uint4*)&g_Sh[(size_t)w * DD] + lane));  // self-loop
    int j = beg;
    for (; j + 4 <= end; j += 4) {
        int s0 = __ldg(&g_col[j]);
        int s1 = __ldg(&g_col[j + 1]);
        int s2 = __ldg(&g_col[j + 2]);
        int s3 = __ldg(&g_col[j + 3]);
        uint4 u0 = __ldg((const uint4*)&g_Sh[(size_t)s0 * DD] + lane);
        uint4 u1 = __ldg((const uint4*)&g_Sh[(size_t)s1 * DD] + lane);
        uint4 u2 = __ldg((const uint4*)&g_Sh[(size_t)s2 * DD] + lane);
        uint4 u3 = __ldg((const uint4*)&g_Sh[(size_t)s3 * DD] + lane);
        add_h8(acc, u0);
        add_h8(acc, u1);
        add_h8(acc, u2);
        add_h8(acc, u3);
    }
    for (; j < end; j++) {
        int s = __ldg(&g_col[j]);
        add_h8(acc, __ldg((const uint4*)&g_Sh[(size_t)s * DD] + lane));
    }
    float4 b0 = *(const float4*)&bias[lane * 8];
    float4 b1 = *(const float4*)&bias[lane * 8 + 4];
    float o[8];
    o[0] = fmaf(acc[0], dn, b0.x); o[1] = fmaf(acc[1], dn, b0.y);
    o[2] = fmaf(acc[2], dn, b0.z); o[3] = fmaf(acc[3], dn, b0.w);
    o[4] = fmaf(acc[4], dn, b1.x); o[5] = fmaf(acc[5], dn, b1.y);
    o[6] = fmaf(acc[6], dn, b1.z); o[7] = fmaf(acc[7], dn, b1.w);
    if (RELU) {
        #pragma unroll
        for (int i = 0; i < 8; i++) o[i] = fmaxf(o[i], 0.f);
    }
    uint4 pk;
    *reinterpret_cast<__half2*>(&pk.x) = __floats2half2_rn(o[0], o[1]);
    *reinterpret_cast<__half2*>(&pk.y) = __floats2half2_rn(o[2], o[3]);
    *reinterpret_cast<__half2*>(&pk.z) = __floats2half2_rn(o[4], o[5]);
    *reinterpret_cast<__half2*>(&pk.w) = __floats2half2_rn(o[6], o[7]);
    *((uint4*)&g_Hh[(size_t)w * DD] + lane) = pk;
}

// -------- pair dot products: half-warp per pair, uint4 loads --------
__global__ void k_pairs(const int* __restrict__ pos, const int* __restrict__ neg,
                        float* __restrict__ out, int P) {
    int q = (blockIdx.x * blockDim.x + threadIdx.x) >> 4;
    int lane = threadIdx.x & 15;
    if (q >= 2 * P) return;
    const int* tab = (q < P) ? pos : neg;
    int p = (q < P) ? q : q - P;
    int a = __ldg(&tab[2 * p]);
    int b = __ldg(&tab[2 * p + 1]);
    uint4 ua = __ldg((const uint4*)&g_Hh[(size_t)a * DD] + lane);
    uint4 ub = __ldg((const uint4*)&g_Hh[(size_t)b * DD] + lane);
    float2 a0 = __half22float2(*reinterpret_cast<__half2*>(&ua.x));
    float2 a1 = __half22float2(*reinterpret_cast<__half2*>(&ua.y));
    float2 a2 = __half22float2(*reinterpret_cast<__half2*>(&ua.z));
    float2 a3 = __half22float2(*reinterpret_cast<__half2*>(&ua.w));
    float2 c0 = __half22float2(*reinterpret_cast<__half2*>(&ub.x));
    float2 c1 = __half22float2(*reinterpret_cast<__half2*>(&ub.y));
    float2 c2 = __half22float2(*reinterpret_cast<__half2*>(&ub.z));
    float2 c3 = __half22float2(*reinterpret_cast<__half2*>(&ub.w));
    float d = a0.x * c0.x + a0.y * c0.y + a1.x * c1.x + a1.y * c1.y
            + a2.x * c2.x + a2.y * c2.y + a3.x * c3.x + a3.y * c3.y;
    #pragma unroll
    for (int off = 8; off; off >>= 1) d += __shfl_xor_sync(0xffffffffu, d, off);
    if (lane == 0) out[q] = d;
}

extern "C" void kernel_launch(void* const* d_in, const int* in_sizes, int n_in,
                              void* d_out, int out_size) {
    const float* x   = (const float*)d_in[0];
    const float* W1  = (const float*)d_in[1];
    const float* b1  = (const float*)d_in[2];
    const float* W2  = (const float*)d_in[3];
    const float* b2  = (const float*)d_in[4];
    const int* ei    = (const int*)d_in[5];
    const int* edges = (const int*)d_in[6];
    const int* edneg = (const int*)d_in[7];
    float* out = (float*)d_out;

    int E = in_sizes[5] / 2;
    int P = in_sizes[6] / 2;
    const int* src = ei;
    const int* dst = ei + E;

    static cudaStream_t s2 = nullptr;
    static cudaEvent_t evFork = nullptr, evJoin = nullptr;
    if (!s2) {
        cudaStreamCreateWithFlags(&s2, cudaStreamNonBlocking);
        cudaEventCreateWithFlags(&evFork, cudaEventDisableTiming);
        cudaEventCreateWithFlags(&evJoin, cudaEventDisableTiming);
        cudaFuncSetAttribute((const void*)k_gemm<float, true, false>,
                             cudaFuncAttributeMaxDynamicSharedMemorySize, GSMEM);
        cudaFuncSetAttribute((const void*)k_gemm<__half, false, true>,
                             cudaFuncAttributeMaxDynamicSharedMemorySize, GSMEM);
    }

    void *pSh = nullptr, *pHh = nullptr, *pWf1 = nullptr, *pWf2 = nullptr, *pCnt = nullptr;
    cudaGetSymbolAddress(&pSh, g_Sh);
    cudaGetSymbolAddress(&pHh, g_Hh);
    cudaGetSymbolAddress(&pWf1, g_Wf1);
    cudaGetSymbolAddress(&pWf2, g_Wf2);
    cudaGetSymbolAddress(&pCnt, g_count);

    // ---- fork: CSR build on side stream s2 ----
    cudaEventRecord(evFork, 0);
    cudaStreamWaitEvent(s2, evFork, 0);
    cudaMemsetAsync(pCnt, 0, NN * sizeof(int), s2);
    k_degree<<<(E / 4 + 256) / 256, 256, 0, s2>>>(dst, E);
    k_scan1<<<NB_SCAN, 1024, 0, s2>>>(NN);
    k_scan2<<<1, 128, 0, s2>>>(NB_SCAN);
    k_scan3<<<(NN + 255) / 256, 256, 0, s2>>>(NN, E);
    k_bucket<<<(E / 2 + 256) / 256, 256, 0, s2>>>(src, dst, E);
    cudaEventRecord(evJoin, s2);

    // ---- main stream: W split + GEMM1 (independent of CSR) ----
    int gemm_blocks = (NN + 127) / 128;
    k_wsplit<<<(8 * 16 * 32 + 255) / 256, 256>>>(W1, (uint4*)pWf1);
    k_wsplit<<<(8 * 16 * 32 + 255) / 256, 256>>>(W2, (uint4*)pWf2);
    k_gemm<float, true, false><<<gemm_blocks, 1024, GSMEM>>>(x, (const uint4*)pWf1,
                                                             (__half*)pSh, NN);

    // ---- join, then dependent chain ----
    cudaStreamWaitEvent(0, evJoin, 0);

    int gather_blocks = (NN * 16 + 255) / 256;
    k_scale<<<(NN * 16 + 255) / 256, 256>>>(NN);
    k_gather<true><<<gather_blocks, 256>>>(b1, NN);
    k_gemm<__half, false, true><<<gemm_blocks, 1024, GSMEM>>>((const __half*)pHh,
                                                              (const uint4*)pWf2,
                                                              (__half*)pSh, NN);
    k_gather<false><<<gather_blocks, 256>>>(b2, NN);
    int pair_blocks = (2 * P * 16 + 255) / 256;
    k_pairs<<<pair_blocks, 256>>>(edges, edneg, out, P);
}

// round 8
// speedup vs baseline: 1.8004x; 1.0173x over previous
#include <cuda_runtime.h>
#include <cuda_fp16.h>

#define NN 100000
#define EE_MAX 1600000
#define DD 128
#define NB_SCAN 98   // ceil(100000/1024)

// -------- scratch (device globals; no allocation allowed) --------
__device__ __half  g_Sh[(size_t)NN * DD];  // GEMM out (prescaled by dinv), fp16
__device__ __half  g_Hh[(size_t)NN * DD];  // layer output, fp16
__device__ float   g_dinv[NN];
__device__ int     g_count[NN];
__device__ int     g_rowptr[NN + 1];
__device__ int     g_cursor[NN];
__device__ int     g_col[EE_MAX];
__device__ int     g_bsum[NB_SCAN];
__device__ int     g_boff[NB_SCAN];
__device__ int     g_scanctr;
// W in fp16 hi/lo mma-fragment order: per (kt,ntg,lane) uint4 {b0hi2,b1hi2,b0lo2,b1lo2}
__device__ uint4   g_Wf1[8 * 16 * 32];
__device__ uint4   g_Wf2[8 * 16 * 32];

__device__ __forceinline__ unsigned packh2(__half a, __half b) {
    __half2 h = __halves2half2(a, b);
    return *reinterpret_cast<unsigned*>(&h);
}

__device__ __forceinline__ void mma16(float* c, const unsigned* a, const unsigned* b) {
    asm volatile(
        "mma.sync.aligned.m16n8k16.row.col.f32.f16.f16.f32 "
        "{%0,%1,%2,%3}, {%4,%5,%6,%7}, {%8,%9}, {%0,%1,%2,%3};\n"
        : "+f"(c[0]), "+f"(c[1]), "+f"(c[2]), "+f"(c[3])
        : "r"(a[0]), "r"(a[1]), "r"(a[2]), "r"(a[3]), "r"(b[0]), "r"(b[1]));
}

// -------- CSR build --------
__global__ void k_degree(const int* __restrict__ dst, int E) {
    int i = blockIdx.x * blockDim.x + threadIdx.x;
    if (i == 0) g_scanctr = 0;   // reset last-block counter for fused scan (pre-scan1 on stream)
    int e = i * 4;
    if (e + 4 <= E) {
        int4 d = *(const int4*)&dst[e];
        atomicAdd(&g_count[d.x], 1);
        atomicAdd(&g_count[d.y], 1);
        atomicAdd(&g_count[d.z], 1);
        atomicAdd(&g_count[d.w], 1);
    } else {
        for (; e < E; e++) atomicAdd(&g_count[dst[e]], 1);
    }
}

// block-local exclusive scan + dinv; last block scans the block sums (fused scan2)
__global__ void k_scan1(int n) {
    __shared__ int s[1024];
    __shared__ int isLast;
    int i = blockIdx.x * 1024 + threadIdx.x;
    int v = (i < n) ? g_count[i] : 0;
    if (i < n) g_dinv[i] = rsqrtf((float)v + 1.0f);  // +1 self-loop
    s[threadIdx.x] = v;
    __syncthreads();
    #pragma unroll
    for (int off = 1; off < 1024; off <<= 1) {
        int t = (threadIdx.x >= off) ? s[threadIdx.x - off] : 0;
        __syncthreads();
        s[threadIdx.x] += t;
        __syncthreads();
    }
    if (i < n) g_rowptr[i] = s[threadIdx.x] - v;  // exclusive within block
    if (threadIdx.x == 1023) g_bsum[blockIdx.x] = s[1023];
    __threadfence();
    if (threadIdx.x == 0) isLast = (atomicAdd(&g_scanctr, 1) == gridDim.x - 1);
    __syncthreads();
    if (isLast) {   // whole last block enters (isLast is shared)
        int t = threadIdx.x;
        int bv = (t < NB_SCAN) ? g_bsum[t] : 0;
        if (t < 128) s[t] = bv;
        __syncthreads();
        #pragma unroll
        for (int off = 1; off < 128; off <<= 1) {
            int tv = (t < 128 && t >= off) ? s[t - off] : 0;
            __syncthreads();
            if (t < 128) s[t] += tv;
            __syncthreads();
        }
        if (t < NB_SCAN) g_boff[t] = s[t] - bv;  // exclusive block offsets
    }
}

__global__ void k_scan3(int n, int E) {
    int i = blockIdx.x * blockDim.x + threadIdx.x;
    if (i < n) {
        int r = g_rowptr[i] + g_boff[i >> 10];
        g_rowptr[i] = r;
        g_cursor[i] = r;
    }
    if (i == 0) g_rowptr[n] = E;
}

__global__ void k_bucket(const int* __restrict__ src, const int* __restrict__ dst, int E) {
    int i = blockIdx.x * blockDim.x + threadIdx.x;
    int e = i * 2;
    if (e + 2 <= E) {
        int2 s = *(const int2*)&src[e];
        int2 d = *(const int2*)&dst[e];
        int p0 = atomicAdd(&g_cursor[d.x], 1);
        g_col[p0] = s.x;
        int p1 = atomicAdd(&g_cursor[d.y], 1);
        g_col[p1] = s.y;
    } else {
        for (; e < E; e++) {
            int pos = atomicAdd(&g_cursor[dst[e]], 1);
            g_col[pos] = src[e];
        }
    }
}

// -------- W -> fp16 hi/lo fragment split (m16n8k16 B layout) --------
__global__ void k_wsplit(const float* __restrict__ W, uint4* __restrict__ out) {
    int i = blockIdx.x * blockDim.x + threadIdx.x;
    if (i >= 8 * 16 * 32) return;
    int lane = i & 31;
    int tile = i >> 5;
    int ntg = tile & 15;
    int kt = tile >> 4;
    int tig = lane & 3, g = lane >> 2;
    int k0 = kt * 16, n0 = ntg * 8;
    float w00 = W[(k0 + 2 * tig) * DD + n0 + g];
    float w01 = W[(k0 + 2 * tig + 1) * DD + n0 + g];
    float w10 = W[(k0 + 2 * tig + 8) * DD + n0 + g];
    float w11 = W[(k0 + 2 * tig + 9) * DD + n0 + g];
    __half h00 = __float2half_rn(w00), h01 = __float2half_rn(w01);
    __half h10 = __float2half_rn(w10), h11 = __float2half_rn(w11);
    __half l00 = __float2half_rn(w00 - __half2float(h00));
    __half l01 = __float2half_rn(w01 - __half2float(h01));
    __half l10 = __float2half_rn(w10 - __half2float(h10));
    __half l11 = __float2half_rn(w11 - __half2float(h11));
    uint4 o;
    o.x = packh2(h00, h01);
    o.y = packh2(h10, h11);
    o.z = packh2(l00, l01);
    o.w = packh2(l10, l11);
    out[i] = o;
}

// -------- GEMM (split-fp16 tensor core), dinv prescale in epilogue --------
// SPLIT_A: fp32 input (layer 1; 3 mma) vs fp16-exact input (layer 2; 2 mma)
#define GSMEM (128 * 132 * 4 + 8 * 16 * 32 * 16)   // 133120

template <typename IN, bool SPLIT_A>
__global__ void __launch_bounds__(1024, 1)
k_gemm(const IN* __restrict__ X, const uint4* __restrict__ Wfrag,
       __half* __restrict__ out, int n) {
    extern __shared__ float sm[];
    float* sX = sm;                         // 128 x 132 (padded) fp32
    uint4* sW = (uint4*)(sm + 128 * 132);   // 8*16*32 fragment uint4s
    int t = threadIdx.x;
    int row0 = blockIdx.x * 128;

    #pragma unroll
    for (int j = t; j < 4096; j += 1024) sW[j] = Wfrag[j];
    #pragma unroll
    for (int j = t; j < 4096; j += 1024) {
        int r = j >> 5, c4 = j & 31;
        int gr = row0 + r;
        float4 v = make_float4(0.f, 0.f, 0.f, 0.f);
        if (gr < n) {
            if constexpr (sizeof(IN) == 4) {
                v = *(const float4*)&X[(size_t)gr * DD + c4 * 4];
            } else {
                uint2 u = *(const uint2*)&X[(size_t)gr * DD + c4 * 4];
                float2 f0 = __half22float2(*reinterpret_cast<__half2*>(&u.x));
                float2 f1 = __half22float2(*reinterpret_cast<__half2*>(&u.y));
                v = make_float4(f0.x, f0.y, f1.x, f1.y);
            }
        }
        *(float4*)&sX[r * 132 + c4 * 4] = v;
    }
    __syncthreads();

    int lane = t & 31, wid = t >> 5;
    int wr = wid >> 2, wc = wid & 3;
    int g = lane >> 2, tig = lane & 3;

    float c[4][4];
    #pragma unroll
    for (int i = 0; i < 4; i++)
        #pragma unroll
        for (int j = 0; j < 4; j++) c[i][j] = 0.f;

    const float* xb = &sX[(wr * 16 + g) * 132];

    #pragma unroll
    for (int kt = 0; kt < 8; kt++) {
        int k0 = kt * 16;
        float2 p0 = *(const float2*)&xb[k0 + 2 * tig];
        float2 p1 = *(const float2*)&xb[8 * 132 + k0 + 2 * tig];
        float2 p2 = *(const float2*)&xb[k0 + 2 * tig + 8];
        float2 p3 = *(const float2*)&xb[8 * 132 + k0 + 2 * tig + 8];
        __half h00 = __float2half_rn(p0.x), h01 = __float2half_rn(p0.y);
        __half h10 = __float2half_rn(p1.x), h11 = __float2half_rn(p1.y);
        __half h20 = __float2half_rn(p2.x), h21 = __float2half_rn(p2.y);
        __half h30 = __float2half_rn(p3.x), h31 = __float2half_rn(p3.y);
        unsigned ah[4], al[4];
        ah[0] = packh2(h00, h01);
        ah[1] = packh2(h10, h11);
        ah[2] = packh2(h20, h21);
        ah[3] = packh2(h30, h31);
        if constexpr (SPLIT_A) {
            al[0] = packh2(__float2half_rn(p0.x - __half2float(h00)),
                           __float2half_rn(p0.y - __half2float(h01)));
            al[1] = packh2(__float2half_rn(p1.x - __half2float(h10)),
                           __float2half_rn(p1.y - __half2float(h11)));
            al[2] = packh2(__float2half_rn(p2.x - __half2float(h20)),
                           __float2half_rn(p2.y - __half2float(h21)));
            al[3] = packh2(__float2half_rn(p3.x - __half2float(h30)),
                           __float2half_rn(p3.y - __half2float(h31)));
        }
        #pragma unroll
        for (int nt = 0; nt < 4; nt++) {
            uint4 bf = sW[(kt * 16 + wc * 4 + nt) * 32 + lane];
            unsigned bh[2] = {bf.x, bf.y};
            unsigned bl[2] = {bf.z, bf.w};
            mma16(c[nt], ah, bh);
            if constexpr (SPLIT_A) mma16(c[nt], al, bh);
            mma16(c[nt], ah, bl);
        }
    }

    int ra = row0 + wr * 16 + g;
    int rb = ra + 8;
    float sa = (ra < n) ? g_dinv[ra] : 1.f;
    float sb = (rb < n) ? g_dinv[rb] : 1.f;
    #pragma unroll
    for (int nt = 0; nt < 4; nt++) {
        int col = wc * 32 + nt * 8 + tig * 2;
        if (ra < n) *(__half2*)&out[(size_t)ra * DD + col] =
            __floats2half2_rn(c[nt][0] * sa, c[nt][1] * sa);
        if (rb < n) *(__half2*)&out[(size_t)rb * DD + col] =
            __floats2half2_rn(c[nt][2] * sb, c[nt][3] * sb);
    }
}

// -------- gather over prescaled rows: H[w] = act( dinv[w]*Σ_{s∈N(w)∪{w}} Sh[s] + b ) ----
__device__ __forceinline__ void add_h8(float* acc, uint4 u) {
    float2 f0 = __half22float2(*reinterpret_cast<__half2*>(&u.x));
    float2 f1 = __half22float2(*reinterpret_cast<__half2*>(&u.y));
    float2 f2 = __half22float2(*reinterpret_cast<__half2*>(&u.z));
    float2 f3 = __half22float2(*reinterpret_cast<__half2*>(&u.w));
    acc[0] += f0.x; acc[1] += f0.y;
    acc[2] += f1.x; acc[3] += f1.y;
    acc[4] += f2.x; acc[5] += f2.y;
    acc[6] += f3.x; acc[7] += f3.y;
}

template <bool RELU>
__global__ void k_gather(const float* __restrict__ bias, int n) {
    int w = (blockIdx.x * blockDim.x + threadIdx.x) >> 4;   // node = half-warp
    int lane = threadIdx.x & 15;                            // 16 lanes x 16B = 256B row
    if (w >= n) return;
    int beg = g_rowptr[w];
    int end = g_rowptr[w + 1];
    float dn = g_dinv[w];
    float acc[8] = {0.f, 0.f, 0.f, 0.f, 0.f, 0.f, 0.f, 0.f};
    add_h8(acc, __ldg((const uint4*)&g_Sh[(size_t)w * DD] + lane));  // self-loop
    int j = beg;
    for (; j + 4 <= end; j += 4) {
        int s0 = __ldg(&g_col[j]);
        int s1 = __ldg(&g_col[j + 1]);
        int s2 = __ldg(&g_col[j + 2]);
        int s3 = __ldg(&g_col[j + 3]);
        uint4 u0 = __ldg((const uint4*)&g_Sh[(size_t)s0 * DD] + lane);
        uint4 u1 = __ldg((const uint4*)&g_Sh[(size_t)s1 * DD] + lane);
        uint4 u2 = __ldg((const uint4*)&g_Sh[(size_t)s2 * DD] + lane);
        uint4 u3 = __ldg((const uint4*)&g_Sh[(size_t)s3 * DD] + lane);
        add_h8(acc, u0);
        add_h8(acc, u1);
        add_h8(acc, u2);
        add_h8(acc, u3);
    }
    for (; j < end; j++) {
        int s = __ldg(&g_col[j]);
        add_h8(acc, __ldg((const uint4*)&g_Sh[(size_t)s * DD] + lane));
    }
    float4 b0 = *(const float4*)&bias[lane * 8];
    float4 b1 = *(const float4*)&bias[lane * 8 + 4];
    float o[8];
    o[0] = fmaf(acc[0], dn, b0.x); o[1] = fmaf(acc[1], dn, b0.y);
    o[2] = fmaf(acc[2], dn, b0.z); o[3] = fmaf(acc[3], dn, b0.w);
    o[4] = fmaf(acc[4], dn, b1.x); o[5] = fmaf(acc[5], dn, b1.y);
    o[6] = fmaf(acc[6], dn, b1.z); o[7] = fmaf(acc[7], dn, b1.w);
    if (RELU) {
        #pragma unroll
        for (int i = 0; i < 8; i++) o[i] = fmaxf(o[i], 0.f);
    }
    uint4 pk;
    *reinterpret_cast<__half2*>(&pk.x) = __floats2half2_rn(o[0], o[1]);
    *reinterpret_cast<__half2*>(&pk.y) = __floats2half2_rn(o[2], o[3]);
    *reinterpret_cast<__half2*>(&pk.z) = __floats2half2_rn(o[4], o[5]);
    *reinterpret_cast<__half2*>(&pk.w) = __floats2half2_rn(o[6], o[7]);
    *((uint4*)&g_Hh[(size_t)w * DD] + lane) = pk;
}

// -------- pair dot products: half-warp per pair, uint4 loads --------
__global__ void k_pairs(const int* __restrict__ pos, const int* __restrict__ neg,
                        float* __restrict__ out, int P) {
    int q = (blockIdx.x * blockDim.x + threadIdx.x) >> 4;
    int lane = threadIdx.x & 15;
    if (q >= 2 * P) return;
    const int* tab = (q < P) ? pos : neg;
    int p = (q < P) ? q : q - P;
    int a = __ldg(&tab[2 * p]);
    int b = __ldg(&tab[2 * p + 1]);
    uint4 ua = __ldg((const uint4*)&g_Hh[(size_t)a * DD] + lane);
    uint4 ub = __ldg((const uint4*)&g_Hh[(size_t)b * DD] + lane);
    float2 a0 = __half22float2(*reinterpret_cast<__half2*>(&ua.x));
    float2 a1 = __half22float2(*reinterpret_cast<__half2*>(&ua.y));
    float2 a2 = __half22float2(*reinterpret_cast<__half2*>(&ua.z));
    float2 a3 = __half22float2(*reinterpret_cast<__half2*>(&ua.w));
    float2 c0 = __half22float2(*reinterpret_cast<__half2*>(&ub.x));
    float2 c1 = __half22float2(*reinterpret_cast<__half2*>(&ub.y));
    float2 c2 = __half22float2(*reinterpret_cast<__half2*>(&ub.z));
    float2 c3 = __half22float2(*reinterpret_cast<__half2*>(&ub.w));
    float d = a0.x * c0.x + a0.y * c0.y + a1.x * c1.x + a1.y * c1.y
            + a2.x * c2.x + a2.y * c2.y + a3.x * c3.x + a3.y * c3.y;
    #pragma unroll
    for (int off = 8; off; off >>= 1) d += __shfl_xor_sync(0xffffffffu, d, off);
    if (lane == 0) out[q] = d;
}

extern "C" void kernel_launch(void* const* d_in, const int* in_sizes, int n_in,
                              void* d_out, int out_size) {
    const float* x   = (const float*)d_in[0];
    const float* W1  = (const float*)d_in[1];
    const float* b1  = (const float*)d_in[2];
    const float* W2  = (const float*)d_in[3];
    const float* b2  = (const float*)d_in[4];
    const int* ei    = (const int*)d_in[5];
    const int* edges = (const int*)d_in[6];
    const int* edneg = (const int*)d_in[7];
    float* out = (float*)d_out;

    int E = in_sizes[5] / 2;
    int P = in_sizes[6] / 2;
    const int* src = ei;
    const int* dst = ei + E;

    static cudaStream_t s2 = nullptr;
    static cudaEvent_t evFork = nullptr, evDinv = nullptr, evJoin = nullptr;
    if (!s2) {
        cudaStreamCreateWithFlags(&s2, cudaStreamNonBlocking);
        cudaEventCreateWithFlags(&evFork, cudaEventDisableTiming);
        cudaEventCreateWithFlags(&evDinv, cudaEventDisableTiming);
        cudaEventCreateWithFlags(&evJoin, cudaEventDisableTiming);
        cudaFuncSetAttribute((const void*)k_gemm<float, true>,
                             cudaFuncAttributeMaxDynamicSharedMemorySize, GSMEM);
        cudaFuncSetAttribute((const void*)k_gemm<__half, false>,
                             cudaFuncAttributeMaxDynamicSharedMemorySize, GSMEM);
    }

    void *pSh = nullptr, *pHh = nullptr, *pWf1 = nullptr, *pWf2 = nullptr, *pCnt = nullptr;
    cudaGetSymbolAddress(&pSh, g_Sh);
    cudaGetSymbolAddress(&pHh, g_Hh);
    cudaGetSymbolAddress(&pWf1, g_Wf1);
    cudaGetSymbolAddress(&pWf2, g_Wf2);
    cudaGetSymbolAddress(&pCnt, g_count);

    // ---- fork: CSR build on side stream s2 ----
    cudaEventRecord(evFork, 0);
    cudaStreamWaitEvent(s2, evFork, 0);
    cudaMemsetAsync(pCnt, 0, NN * sizeof(int), s2);
    k_degree<<<(E / 4 + 256) / 256, 256, 0, s2>>>(dst, E);
    k_scan1<<<NB_SCAN, 1024, 0, s2>>>(NN);          // also computes dinv + fused scan2
    cudaEventRecord(evDinv, s2);                    // dinv ready for GEMM1 epilogue
    k_scan3<<<(NN + 255) / 256, 256, 0, s2>>>(NN, E);
    k_bucket<<<(E / 2 + 256) / 256, 256, 0, s2>>>(src, dst, E);
    cudaEventRecord(evJoin, s2);

    // ---- main stream: W split + GEMM1 (needs only dinv from side chain) ----
    int gemm_blocks = (NN + 127) / 128;
    k_wsplit<<<(8 * 16 * 32 + 255) / 256, 256>>>(W1, (uint4*)pWf1);
    k_wsplit<<<(8 * 16 * 32 + 255) / 256, 256>>>(W2, (uint4*)pWf2);
    cudaStreamWaitEvent(0, evDinv, 0);
    k_gemm<float, true><<<gemm_blocks, 1024, GSMEM>>>(x, (const uint4*)pWf1,
                                                      (__half*)pSh, NN);

    // ---- join (CSR complete), then dependent chain ----
    cudaStreamWaitEvent(0, evJoin, 0);

    int gather_blocks = (NN * 16 + 255) / 256;
    k_gather<true><<<gather_blocks, 256>>>(b1, NN);
    k_gemm<__half, false><<<gemm_blocks, 1024, GSMEM>>>((const __half*)pHh,
                                                        (const uint4*)pWf2,
                                                        (__half*)pSh, NN);
    k_gather<false><<<gather_blocks, 256>>>(b2, NN);
    int pair_blocks = (2 * P * 16 + 255) / 256;
    k_pairs<<<pair_blocks, 256>>>(edges, edneg, out, P);
}